// round 7
// baseline (speedup 1.0000x reference)
#include <cuda_runtime.h>
#include <cuda_bf16.h>
#include <cstdint>

#define B_   2
#define S_   2048
#define H_   16
#define D_   64
#define E_   1024
#define TE_  3072
#define MTOT (B_ * S_)   // 4096

// ---------------------------------------------------------------------------
// Scratch (__device__ globals; no allocation allowed)
// ---------------------------------------------------------------------------
__device__ __nv_bfloat16 g_qkv_hi[(size_t)MTOT * TE_];
__device__ __nv_bfloat16 g_qkv_lo[(size_t)MTOT * TE_];
__device__ __nv_bfloat16 g_o_hi[(size_t)MTOT * E_];
__device__ __nv_bfloat16 g_o_lo[(size_t)MTOT * E_];
__device__ __nv_bfloat16 g_x_hi[(size_t)MTOT * E_];
__device__ __nv_bfloat16 g_x_lo[(size_t)MTOT * E_];
__device__ __nv_bfloat16 g_wq_hi[(size_t)TE_ * E_];
__device__ __nv_bfloat16 g_wq_lo[(size_t)TE_ * E_];
__device__ __nv_bfloat16 g_wo_hi[(size_t)E_ * E_];
__device__ __nv_bfloat16 g_wo_lo[(size_t)E_ * E_];

// ---------------------------------------------------------------------------
// Helpers (sm_80-level PTX only)
// ---------------------------------------------------------------------------
__device__ __forceinline__ uint32_t smem_u32(const void* p) {
    uint32_t a;
    asm("{ .reg .u64 t; cvta.to.shared.u64 t, %1; cvt.u32.u64 %0, t; }" : "=r"(a) : "l"(p));
    return a;
}
__device__ __forceinline__ uint32_t pk2(float a, float b) {
    __nv_bfloat162 t = __floats2bfloat162_rn(a, b);
    return *reinterpret_cast<uint32_t*>(&t);
}
__device__ __forceinline__ uint32_t pkh(__nv_bfloat16 a, __nv_bfloat16 b) {
    __nv_bfloat162 t(a, b);
    return *reinterpret_cast<uint32_t*>(&t);
}
__device__ __forceinline__ void ldm_x4(uint32_t* r, uint32_t addr) {
    asm volatile("ldmatrix.sync.aligned.m8n8.x4.shared.b16 {%0,%1,%2,%3}, [%4];"
                 : "=r"(r[0]), "=r"(r[1]), "=r"(r[2]), "=r"(r[3]) : "r"(addr));
}
__device__ __forceinline__ void ldm_x4t(uint32_t* r, uint32_t addr) {
    asm volatile("ldmatrix.sync.aligned.m8n8.x4.trans.shared.b16 {%0,%1,%2,%3}, [%4];"
                 : "=r"(r[0]), "=r"(r[1]), "=r"(r[2]), "=r"(r[3]) : "r"(addr));
}
__device__ __forceinline__ void mma16816(float* c, const uint32_t* a, const uint32_t* b) {
    asm volatile(
        "mma.sync.aligned.m16n8k16.row.col.f32.bf16.bf16.f32 "
        "{%0,%1,%2,%3}, {%4,%5,%6,%7}, {%8,%9}, {%0,%1,%2,%3};"
        : "+f"(c[0]), "+f"(c[1]), "+f"(c[2]), "+f"(c[3])
        : "r"(a[0]), "r"(a[1]), "r"(a[2]), "r"(a[3]), "r"(b[0]), "r"(b[1]));
}
__device__ __forceinline__ void cp_async16(uint32_t saddr, const void* gaddr) {
    asm volatile("cp.async.cg.shared.global [%0], [%1], 16;" :: "r"(saddr), "l"(gaddr) : "memory");
}
__device__ __forceinline__ void cp_commit() {
    asm volatile("cp.async.commit_group;" ::: "memory");
}
#define CP_WAIT(n) asm volatile("cp.async.wait_group %0;" :: "n"(n) : "memory")

// 128B-row XOR swizzle (8x16B groups), conflict-free for ldmatrix
__device__ __forceinline__ uint32_t sw128(uint32_t row, uint32_t kg) {
    return row * 128u + ((kg ^ (row & 7u)) << 4);
}

// ---------------------------------------------------------------------------
// fp32 -> bf16 hi + bf16 lo split
// ---------------------------------------------------------------------------
__global__ __launch_bounds__(256)
void split_bf16x2(const float* __restrict__ in, __nv_bfloat16* __restrict__ hi,
                  __nv_bfloat16* __restrict__ lo, int n4)
{
    int i = blockIdx.x * blockDim.x + threadIdx.x;
    if (i >= n4) return;
    float4 v = ((const float4*)in)[i];
    __nv_bfloat16 h0 = __float2bfloat16_rn(v.x);
    __nv_bfloat16 h1 = __float2bfloat16_rn(v.y);
    __nv_bfloat16 h2 = __float2bfloat16_rn(v.z);
    __nv_bfloat16 h3 = __float2bfloat16_rn(v.w);
    uint2 hp = make_uint2(pkh(h0, h1), pkh(h2, h3));
    uint2 lp = make_uint2(pk2(v.x - __bfloat162float(h0), v.y - __bfloat162float(h1)),
                          pk2(v.z - __bfloat162float(h2), v.w - __bfloat162float(h3)));
    *(uint2*)(hi + (size_t)i * 4) = hp;
    *(uint2*)(lo + (size_t)i * 4) = lp;
}

// ---------------------------------------------------------------------------
// HMMA split-bf16 GEMM (NT) — R5 proven config.
// 128x64 block tile, 8 warps (32x32 each), BK=64, 2-stage cp.async.
// MODE 0: fp32 C.  MODE 1: bf16 hi/lo split; Q columns (col%192<64) prescaled
// by 1/sqrt(D) when QSCALE=1.
// ---------------------------------------------------------------------------
#define GA3     16384                 // A tile: 128 rows x 128B
#define GB3     8192                  // B tile: 64 rows x 128B
#define GSTAGE3 (2 * GA3 + 2 * GB3)   // 49152
#define GSMEM3  (2 * GSTAGE3)         // 98304

__device__ __forceinline__ void gemm_issue(
    uint32_t sdst, const __nv_bfloat16* Ah, const __nv_bfloat16* Al,
    const __nv_bfloat16* Bh, const __nv_bfloat16* Bl,
    int bm, int bn, int K, int t, int c)
{
    const int kg = t & 7;
    const int r32 = t >> 3;
    const int koff = c * 128;
    #pragma unroll
    for (int i = 0; i < 4; i++) {
        const int row = i * 32 + r32;
        cp_async16(sdst + sw128(row, kg),
                   (const char*)(Ah + (size_t)(bm + row) * K) + kg * 16 + koff);
        cp_async16(sdst + GA3 + sw128(row, kg),
                   (const char*)(Al + (size_t)(bm + row) * K) + kg * 16 + koff);
    }
    #pragma unroll
    for (int i = 0; i < 2; i++) {
        const int row = i * 32 + r32;
        cp_async16(sdst + 2 * GA3 + sw128(row, kg),
                   (const char*)(Bh + (size_t)(bn + row) * K) + kg * 16 + koff);
        cp_async16(sdst + 2 * GA3 + GB3 + sw128(row, kg),
                   (const char*)(Bl + (size_t)(bn + row) * K) + kg * 16 + koff);
    }
    cp_commit();
}

template <int MODE, int QSCALE>
__global__ __launch_bounds__(256, 2)
void gemm_mma(const __nv_bfloat16* __restrict__ Ah, const __nv_bfloat16* __restrict__ Al,
              const __nv_bfloat16* __restrict__ Bh, const __nv_bfloat16* __restrict__ Bl,
              const float* __restrict__ bias, float* __restrict__ C,
              __nv_bfloat16* __restrict__ Chi, __nv_bfloat16* __restrict__ Clo,
              int N, int K)
{
    extern __shared__ char smem[];
    const uint32_t sb = smem_u32(smem);
    const int t = threadIdx.x;
    const int wid = t >> 5;
    const int lane = t & 31;
    const int bm = blockIdx.y * 128;
    const int bn = blockIdx.x * 64;
    const int wm = (wid >> 1) * 32;
    const int wn = (wid & 1) * 32;

    float acc[2][4][4];
    #pragma unroll
    for (int mt = 0; mt < 2; mt++)
        #pragma unroll
        for (int nt = 0; nt < 4; nt++)
            #pragma unroll
            for (int j = 0; j < 4; j++) acc[mt][nt][j] = 0.f;

    const int niter = K >> 6;

    gemm_issue(sb, Ah, Al, Bh, Bl, bm, bn, K, t, 0);

    for (int c = 0; c < niter; c++) {
        if (c + 1 < niter) {
            gemm_issue(sb + ((c + 1) & 1) * GSTAGE3, Ah, Al, Bh, Bl, bm, bn, K, t, c + 1);
            CP_WAIT(1);
        } else {
            CP_WAIT(0);
        }
        __syncthreads();

        const uint32_t stage = sb + (c & 1) * GSTAGE3;
        #pragma unroll
        for (int ks = 0; ks < 4; ks++) {
            uint32_t ah[2][4], al[2][4], bh[2][4], bl[2][4];
            #pragma unroll
            for (int mt = 0; mt < 2; mt++) {
                uint32_t off = sw128(wm + mt * 16 + (lane & 15), ks * 2 + (lane >> 4));
                ldm_x4(ah[mt], stage + off);
                ldm_x4(al[mt], stage + GA3 + off);
            }
            #pragma unroll
            for (int p = 0; p < 2; p++) {
                uint32_t off = sw128(wn + (p * 2 + (lane >> 4)) * 8 + (lane & 7),
                                     ks * 2 + ((lane >> 3) & 1));
                ldm_x4(bh[p], stage + 2 * GA3 + off);
                ldm_x4(bl[p], stage + 2 * GA3 + GB3 + off);
            }
            #pragma unroll
            for (int mt = 0; mt < 2; mt++)
                #pragma unroll
                for (int nt = 0; nt < 4; nt++) {
                    const uint32_t* bhf = &bh[nt >> 1][(nt & 1) * 2];
                    const uint32_t* blf = &bl[nt >> 1][(nt & 1) * 2];
                    mma16816(acc[mt][nt], ah[mt], bhf);
                    mma16816(acc[mt][nt], ah[mt], blf);
                    mma16816(acc[mt][nt], al[mt], bhf);
                }
        }
        __syncthreads();
    }

    // epilogue
    #pragma unroll
    for (int mt = 0; mt < 2; mt++) {
        const int r0 = bm + wm + mt * 16 + (lane >> 2);
        #pragma unroll
        for (int nt = 0; nt < 4; nt++) {
            const int col = bn + wn + nt * 8 + (lane & 3) * 2;
            const float b0 = bias[col], b1 = bias[col + 1];
            float v00 = acc[mt][nt][0] + b0, v01 = acc[mt][nt][1] + b1;
            float v10 = acc[mt][nt][2] + b0, v11 = acc[mt][nt][3] + b1;
            if (MODE == 0) {
                *(float2*)&C[(size_t)r0 * N + col] = make_float2(v00, v01);
                *(float2*)&C[(size_t)(r0 + 8) * N + col] = make_float2(v10, v11);
            } else {
                if (QSCALE) {
                    // Q columns of the [Q|K|V] per-head packing get 1/sqrt(D)
                    const float qs = ((col % 192) < 64) ? 0.125f : 1.0f;
                    v00 *= qs; v01 *= qs; v10 *= qs; v11 *= qs;
                }
                __nv_bfloat16 h00 = __float2bfloat16_rn(v00);
                __nv_bfloat16 h01 = __float2bfloat16_rn(v01);
                __nv_bfloat16 h10 = __float2bfloat16_rn(v10);
                __nv_bfloat16 h11 = __float2bfloat16_rn(v11);
                *(uint32_t*)&Chi[(size_t)r0 * N + col] = pkh(h00, h01);
                *(uint32_t*)&Chi[(size_t)(r0 + 8) * N + col] = pkh(h10, h11);
                *(uint32_t*)&Clo[(size_t)r0 * N + col] =
                    pk2(v00 - __bfloat162float(h00), v01 - __bfloat162float(h01));
                *(uint32_t*)&Clo[(size_t)(r0 + 8) * N + col] =
                    pk2(v10 - __bfloat162float(h10), v11 - __bfloat162float(h11));
            }
        }
    }
}

// ---------------------------------------------------------------------------
// HMMA flash attention: 8 warps, 128 q-rows per CTA, 2 CTAs/SM.
// smem: Qh Ql (128 rows each) + 2 stages{Kh Kl Vh Vl (64 rows each)}.
// Q is pre-scaled by 1/sqrt(D) (done in QKV GEMM epilogue).
// ---------------------------------------------------------------------------
#define AQ      16384                 // Q tile: 128 rows x 128B
#define AT      8192                  // KV tile: 64 rows x 128B
#define ASTAGE  (4 * AT)              // 32768
#define ASMEM   (2 * AQ + 2 * ASTAGE) // 98304

__device__ __forceinline__ void attn_issue_kv(uint32_t sdst, int b, int h, int kt, int t)
{
    const size_t base_off = ((size_t)(b * S_ + kt * 64) * TE_ + h * (3 * D_)) * 2;
    // 2048 slots (4 tiles x 64 rows x 8 kg) over 256 threads -> 8 each
    #pragma unroll
    for (int i = 0; i < 8; i++) {
        const int id = i * 256 + t;
        const int tile = id >> 9;                 // 0:Kh 1:Kl 2:Vh 3:Vl
        const int row = (id >> 3) & 63;
        const int kg = id & 7;
        const __nv_bfloat16* arr = (tile & 1) ? g_qkv_lo : g_qkv_hi;
        const size_t go = base_off + (size_t)row * (TE_ * 2)
                        + ((tile < 2) ? D_ : 2 * D_) * 2 + kg * 16;
        cp_async16(sdst + (uint32_t)tile * AT + sw128(row, kg), (const char*)arr + go);
    }
    cp_commit();
}

__global__ __launch_bounds__(256, 2)
void flash_mma()
{
    extern __shared__ char smem[];
    const uint32_t sb = smem_u32(smem);
    const uint32_t sQh = sb, sQl = sb + AQ;

    const int t = threadIdx.x;
    const int wid = t >> 5;
    const int lane = t & 31;
    const int qt = blockIdx.x, h = blockIdx.y, b = blockIdx.z;

    // prologue: Q (128 rows, hi+lo), then KV stage 0
    {
        const size_t qbase = ((size_t)(b * S_ + qt * 128) * TE_ + h * (3 * D_)) * 2;
        #pragma unroll
        for (int i = 0; i < 8; i++) {
            const int id = i * 256 + t;           // 0..2047
            const int tile = id >> 10;            // 0:Qh 1:Ql
            const int row = (id >> 3) & 127;
            const int kg = id & 7;
            const __nv_bfloat16* arr = tile ? g_qkv_lo : g_qkv_hi;
            const size_t go = qbase + (size_t)row * (TE_ * 2) + kg * 16;
            cp_async16(sb + (uint32_t)tile * AQ + sw128(row, kg), (const char*)arr + go);
        }
        cp_commit();
    }
    attn_issue_kv(sb + 2 * AQ, b, h, 0, t);

    CP_WAIT(1);
    __syncthreads();

    uint32_t aqh[4][4], aql[4][4];
    #pragma unroll
    for (int ks = 0; ks < 4; ks++) {
        uint32_t off = sw128(wid * 16 + (lane & 15), ks * 2 + (lane >> 4));
        ldm_x4(aqh[ks], sQh + off);
        ldm_x4(aql[ks], sQl + off);
    }

    float o[8][4];
    #pragma unroll
    for (int nt = 0; nt < 8; nt++)
        #pragma unroll
        for (int j = 0; j < 4; j++) o[nt][j] = 0.f;
    float m0 = -1e30f, m1 = -1e30f, l0 = 0.f, l1 = 0.f;

    const int NT = S_ / 64;
    for (int kt = 0; kt < NT; kt++) {
        if (kt + 1 < NT) {
            attn_issue_kv(sb + 2 * AQ + ((kt + 1) & 1) * ASTAGE, b, h, kt + 1, t);
            CP_WAIT(1);
        } else {
            CP_WAIT(0);
        }
        __syncthreads();

        const uint32_t st = sb + 2 * AQ + (kt & 1) * ASTAGE;
        const uint32_t stKh = st, stKl = st + AT, stVh = st + 2 * AT, stVl = st + 3 * AT;

        // ---- S = Q K^T (3-term split, fp32 accum); Q pre-scaled ----
        float sc[8][4];
        #pragma unroll
        for (int nt = 0; nt < 8; nt++)
            #pragma unroll
            for (int j = 0; j < 4; j++) sc[nt][j] = 0.f;
        #pragma unroll
        for (int ks = 0; ks < 4; ks++) {
            #pragma unroll
            for (int p = 0; p < 4; p++) {
                uint32_t off = sw128((p * 2 + (lane >> 4)) * 8 + (lane & 7),
                                     ks * 2 + ((lane >> 3) & 1));
                uint32_t bh[4], bl[4];
                ldm_x4(bh, stKh + off);
                ldm_x4(bl, stKl + off);
                mma16816(sc[2 * p], aqh[ks], bh);
                mma16816(sc[2 * p], aqh[ks], bl);
                mma16816(sc[2 * p], aql[ks], bh);
                mma16816(sc[2 * p + 1], aqh[ks], bh + 2);
                mma16816(sc[2 * p + 1], aqh[ks], bl + 2);
                mma16816(sc[2 * p + 1], aql[ks], bh + 2);
            }
        }

        // ---- online softmax ----
        float rx0 = -1e30f, rx1 = -1e30f;
        #pragma unroll
        for (int nt = 0; nt < 8; nt++) {
            rx0 = fmaxf(rx0, fmaxf(sc[nt][0], sc[nt][1]));
            rx1 = fmaxf(rx1, fmaxf(sc[nt][2], sc[nt][3]));
        }
        rx0 = fmaxf(rx0, __shfl_xor_sync(0xffffffffu, rx0, 1));
        rx0 = fmaxf(rx0, __shfl_xor_sync(0xffffffffu, rx0, 2));
        rx1 = fmaxf(rx1, __shfl_xor_sync(0xffffffffu, rx1, 1));
        rx1 = fmaxf(rx1, __shfl_xor_sync(0xffffffffu, rx1, 2));

        const float mn0 = fmaxf(m0, rx0), mn1 = fmaxf(m1, rx1);
        const float s0 = __expf(m0 - mn0), s1 = __expf(m1 - mn1);
        m0 = mn0; m1 = mn1;
        #pragma unroll
        for (int nt = 0; nt < 8; nt++) {
            o[nt][0] *= s0; o[nt][1] *= s0;
            o[nt][2] *= s1; o[nt][3] *= s1;
        }
        float sum0 = 0.f, sum1 = 0.f;
        #pragma unroll
        for (int nt = 0; nt < 8; nt++) {
            sc[nt][0] = __expf(sc[nt][0] - mn0);
            sc[nt][1] = __expf(sc[nt][1] - mn0);
            sc[nt][2] = __expf(sc[nt][2] - mn1);
            sc[nt][3] = __expf(sc[nt][3] - mn1);
            sum0 += sc[nt][0] + sc[nt][1];
            sum1 += sc[nt][2] + sc[nt][3];
        }
        sum0 += __shfl_xor_sync(0xffffffffu, sum0, 1);
        sum0 += __shfl_xor_sync(0xffffffffu, sum0, 2);
        sum1 += __shfl_xor_sync(0xffffffffu, sum1, 1);
        sum1 += __shfl_xor_sync(0xffffffffu, sum1, 2);
        l0 = l0 * s0 + sum0;
        l1 = l1 * s1 + sum1;

        // ---- O += P V (3-term split) ----
        #pragma unroll
        for (int ks = 0; ks < 4; ks++) {
            uint32_t aph[4], apl[4];
            {
                const int j0 = 2 * ks, j1 = 2 * ks + 1;
                __nv_bfloat16 h00 = __float2bfloat16_rn(sc[j0][0]);
                __nv_bfloat16 h01 = __float2bfloat16_rn(sc[j0][1]);
                __nv_bfloat16 h02 = __float2bfloat16_rn(sc[j0][2]);
                __nv_bfloat16 h03 = __float2bfloat16_rn(sc[j0][3]);
                __nv_bfloat16 h10 = __float2bfloat16_rn(sc[j1][0]);
                __nv_bfloat16 h11 = __float2bfloat16_rn(sc[j1][1]);
                __nv_bfloat16 h12 = __float2bfloat16_rn(sc[j1][2]);
                __nv_bfloat16 h13 = __float2bfloat16_rn(sc[j1][3]);
                aph[0] = pkh(h00, h01);
                aph[1] = pkh(h02, h03);
                aph[2] = pkh(h10, h11);
                aph[3] = pkh(h12, h13);
                apl[0] = pk2(sc[j0][0] - __bfloat162float(h00), sc[j0][1] - __bfloat162float(h01));
                apl[1] = pk2(sc[j0][2] - __bfloat162float(h02), sc[j0][3] - __bfloat162float(h03));
                apl[2] = pk2(sc[j1][0] - __bfloat162float(h10), sc[j1][1] - __bfloat162float(h11));
                apl[3] = pk2(sc[j1][2] - __bfloat162float(h12), sc[j1][3] - __bfloat162float(h13));
            }
            #pragma unroll
            for (int p = 0; p < 4; p++) {
                uint32_t off = sw128(ks * 16 + (lane & 15), 2 * p + (lane >> 4));
                uint32_t bh[4], bl[4];
                ldm_x4t(bh, stVh + off);
                ldm_x4t(bl, stVl + off);
                mma16816(o[2 * p], aph, bh);
                mma16816(o[2 * p], aph, bl);
                mma16816(o[2 * p], apl, bh);
                mma16816(o[2 * p + 1], aph, bh + 2);
                mma16816(o[2 * p + 1], aph, bl + 2);
                mma16816(o[2 * p + 1], apl, bh + 2);
            }
        }
        __syncthreads();
    }

    // ---- normalize, split hi/lo, store ----
    const float inv0 = 1.f / l0, inv1 = 1.f / l1;
    const int r0 = b * S_ + qt * 128 + wid * 16 + (lane >> 2);
    #pragma unroll
    for (int nt = 0; nt < 8; nt++) {
        const int col = h * D_ + nt * 8 + (lane & 3) * 2;
        float v00 = o[nt][0] * inv0, v01 = o[nt][1] * inv0;
        float v10 = o[nt][2] * inv1, v11 = o[nt][3] * inv1;
        __nv_bfloat16 h00 = __float2bfloat16_rn(v00);
        __nv_bfloat16 h01 = __float2bfloat16_rn(v01);
        __nv_bfloat16 h10 = __float2bfloat16_rn(v10);
        __nv_bfloat16 h11 = __float2bfloat16_rn(v11);
        *(uint32_t*)&g_o_hi[(size_t)r0 * E_ + col] = pkh(h00, h01);
        *(uint32_t*)&g_o_hi[(size_t)(r0 + 8) * E_ + col] = pkh(h10, h11);
        *(uint32_t*)&g_o_lo[(size_t)r0 * E_ + col] =
            pk2(v00 - __bfloat162float(h00), v01 - __bfloat162float(h01));
        *(uint32_t*)&g_o_lo[(size_t)(r0 + 8) * E_ + col] =
            pk2(v10 - __bfloat162float(h10), v11 - __bfloat162float(h11));
    }
}

// ---------------------------------------------------------------------------
// Launch
// ---------------------------------------------------------------------------
extern "C" void kernel_launch(void* const* d_in, const int* in_sizes, int n_in,
                              void* d_out, int out_size)
{
    const float* x     = (const float*)d_in[0];
    const float* w_qkv = (const float*)d_in[1];
    const float* b_qkv = (const float*)d_in[2];
    const float* w_o   = (const float*)d_in[3];
    const float* b_o   = (const float*)d_in[4];
    float* out = (float*)d_out;

    __nv_bfloat16 *qkv_hi, *qkv_lo, *o_hi, *o_lo;
    __nv_bfloat16 *x_hi, *x_lo, *wq_hi, *wq_lo, *wo_hi, *wo_lo;
    cudaGetSymbolAddress((void**)&qkv_hi, g_qkv_hi);
    cudaGetSymbolAddress((void**)&qkv_lo, g_qkv_lo);
    cudaGetSymbolAddress((void**)&o_hi, g_o_hi);
    cudaGetSymbolAddress((void**)&o_lo, g_o_lo);
    cudaGetSymbolAddress((void**)&x_hi, g_x_hi);
    cudaGetSymbolAddress((void**)&x_lo, g_x_lo);
    cudaGetSymbolAddress((void**)&wq_hi, g_wq_hi);
    cudaGetSymbolAddress((void**)&wq_lo, g_wq_lo);
    cudaGetSymbolAddress((void**)&wo_hi, g_wo_hi);
    cudaGetSymbolAddress((void**)&wo_lo, g_wo_lo);

    cudaFuncSetAttribute((void*)gemm_mma<0,0>, cudaFuncAttributeMaxDynamicSharedMemorySize, GSMEM3);
    cudaFuncSetAttribute((void*)gemm_mma<1,1>, cudaFuncAttributeMaxDynamicSharedMemorySize, GSMEM3);
    cudaFuncSetAttribute((void*)flash_mma, cudaFuncAttributeMaxDynamicSharedMemorySize, ASMEM);

    {
        int n4 = (MTOT * E_) / 4;
        split_bf16x2<<<(n4 + 255) / 256, 256>>>(x, x_hi, x_lo, n4);
        n4 = (TE_ * E_) / 4;
        split_bf16x2<<<(n4 + 255) / 256, 256>>>(w_qkv, wq_hi, wq_lo, n4);
        n4 = (E_ * E_) / 4;
        split_bf16x2<<<(n4 + 255) / 256, 256>>>(w_o, wo_hi, wo_lo, n4);
    }

    {
        dim3 g(TE_ / 64, MTOT / 128);    // 48 x 32
        gemm_mma<1,1><<<g, 256, GSMEM3>>>(x_hi, x_lo, wq_hi, wq_lo, b_qkv,
                                          nullptr, qkv_hi, qkv_lo, TE_, E_);
    }
    {
        dim3 g(S_ / 128, H_, B_);         // 16 x 16 x 2
        flash_mma<<<g, 256, ASMEM>>>();
    }
    {
        dim3 g(E_ / 64, MTOT / 128);      // 16 x 32
        gemm_mma<0,0><<<g, 256, GSMEM3>>>(o_hi, o_lo, wo_hi, wo_lo, b_o,
                                          out, nullptr, nullptr, E_, E_);
    }
}

// round 8
// speedup vs baseline: 1.6801x; 1.6801x over previous
#include <cuda_runtime.h>
#include <cuda_bf16.h>
#include <cstdint>

#define B_   2
#define S_   2048
#define H_   16
#define D_   64
#define E_   1024
#define TE_  3072
#define MTOT (B_ * S_)   // 4096

// ---------------------------------------------------------------------------
// Scratch (__device__ globals; no allocation allowed)
// ---------------------------------------------------------------------------
__device__ __nv_bfloat16 g_qkv_hi[(size_t)MTOT * TE_];
__device__ __nv_bfloat16 g_qkv_lo[(size_t)MTOT * TE_];
__device__ __nv_bfloat16 g_o_hi[(size_t)MTOT * E_];
__device__ __nv_bfloat16 g_o_lo[(size_t)MTOT * E_];
__device__ __nv_bfloat16 g_x_hi[(size_t)MTOT * E_];
__device__ __nv_bfloat16 g_x_lo[(size_t)MTOT * E_];
__device__ __nv_bfloat16 g_wq_hi[(size_t)TE_ * E_];
__device__ __nv_bfloat16 g_wq_lo[(size_t)TE_ * E_];
__device__ __nv_bfloat16 g_wo_hi[(size_t)E_ * E_];
__device__ __nv_bfloat16 g_wo_lo[(size_t)E_ * E_];

// ---------------------------------------------------------------------------
// Helpers (sm_80-level PTX only)
// ---------------------------------------------------------------------------
__device__ __forceinline__ uint32_t smem_u32(const void* p) {
    uint32_t a;
    asm("{ .reg .u64 t; cvta.to.shared.u64 t, %1; cvt.u32.u64 %0, t; }" : "=r"(a) : "l"(p));
    return a;
}
__device__ __forceinline__ uint32_t pk2(float a, float b) {
    __nv_bfloat162 t = __floats2bfloat162_rn(a, b);
    return *reinterpret_cast<uint32_t*>(&t);
}
__device__ __forceinline__ uint32_t pkh(__nv_bfloat16 a, __nv_bfloat16 b) {
    __nv_bfloat162 t(a, b);
    return *reinterpret_cast<uint32_t*>(&t);
}
__device__ __forceinline__ void ldm_x4(uint32_t* r, uint32_t addr) {
    asm volatile("ldmatrix.sync.aligned.m8n8.x4.shared.b16 {%0,%1,%2,%3}, [%4];"
                 : "=r"(r[0]), "=r"(r[1]), "=r"(r[2]), "=r"(r[3]) : "r"(addr));
}
__device__ __forceinline__ void ldm_x4t(uint32_t* r, uint32_t addr) {
    asm volatile("ldmatrix.sync.aligned.m8n8.x4.trans.shared.b16 {%0,%1,%2,%3}, [%4];"
                 : "=r"(r[0]), "=r"(r[1]), "=r"(r[2]), "=r"(r[3]) : "r"(addr));
}
__device__ __forceinline__ void mma16816(float* c, const uint32_t* a, const uint32_t* b) {
    asm volatile(
        "mma.sync.aligned.m16n8k16.row.col.f32.bf16.bf16.f32 "
        "{%0,%1,%2,%3}, {%4,%5,%6,%7}, {%8,%9}, {%0,%1,%2,%3};"
        : "+f"(c[0]), "+f"(c[1]), "+f"(c[2]), "+f"(c[3])
        : "r"(a[0]), "r"(a[1]), "r"(a[2]), "r"(a[3]), "r"(b[0]), "r"(b[1]));
}
__device__ __forceinline__ void cp_async16(uint32_t saddr, const void* gaddr) {
    asm volatile("cp.async.cg.shared.global [%0], [%1], 16;" :: "r"(saddr), "l"(gaddr) : "memory");
}
__device__ __forceinline__ void cp_commit() {
    asm volatile("cp.async.commit_group;" ::: "memory");
}
#define CP_WAIT(n) asm volatile("cp.async.wait_group %0;" :: "n"(n) : "memory")

// 128B-row XOR swizzle (8x16B groups), conflict-free for ldmatrix
__device__ __forceinline__ uint32_t sw128(uint32_t row, uint32_t kg) {
    return row * 128u + ((kg ^ (row & 7u)) << 4);
}

// ---------------------------------------------------------------------------
// fp32 -> bf16 hi + bf16 lo split
// ---------------------------------------------------------------------------
__global__ __launch_bounds__(256)
void split_bf16x2(const float* __restrict__ in, __nv_bfloat16* __restrict__ hi,
                  __nv_bfloat16* __restrict__ lo, int n4)
{
    int i = blockIdx.x * blockDim.x + threadIdx.x;
    if (i >= n4) return;
    float4 v = ((const float4*)in)[i];
    __nv_bfloat16 h0 = __float2bfloat16_rn(v.x);
    __nv_bfloat16 h1 = __float2bfloat16_rn(v.y);
    __nv_bfloat16 h2 = __float2bfloat16_rn(v.z);
    __nv_bfloat16 h3 = __float2bfloat16_rn(v.w);
    uint2 hp = make_uint2(pkh(h0, h1), pkh(h2, h3));
    uint2 lp = make_uint2(pk2(v.x - __bfloat162float(h0), v.y - __bfloat162float(h1)),
                          pk2(v.z - __bfloat162float(h2), v.w - __bfloat162float(h3)));
    *(uint2*)(hi + (size_t)i * 4) = hp;
    *(uint2*)(lo + (size_t)i * 4) = lp;
}

// ---------------------------------------------------------------------------
// HMMA split-bf16 GEMM (NT): C = A[M,K]*B[N,K]^T + bias
// 128xBN block tile (BN = 64 or 96), 8 warps (32 x BN/2 each), BK=64,
// 2-stage cp.async. 2 CTAs/SM.
// MODE 0: fp32 C.  MODE 1: bf16 hi/lo split; QSCALE=1 prescales Q cols
// (col%192 < 64) by 1/sqrt(D).
// ---------------------------------------------------------------------------
#define GA3 16384                     // A tile: 128 rows x 128B

template <int BN>
__device__ __forceinline__ void gemm_issue(
    uint32_t sdst, const __nv_bfloat16* Ah, const __nv_bfloat16* Al,
    const __nv_bfloat16* Bh, const __nv_bfloat16* Bl,
    int bm, int bn, int K, int t, int c)
{
    const int GB = BN * 128;
    const int koff = c * 128;
    // A: 2048 slots (2 tiles x 128 rows x 8 kg)
    #pragma unroll
    for (int i = 0; i < 8; i++) {
        const int id = i * 256 + t;
        const int idm = id & 1023;
        const int row = idm >> 3, kg = idm & 7;
        const __nv_bfloat16* base = (id >> 10) ? Al : Ah;
        const uint32_t so = ((id >> 10) ? GA3 : 0) + sw128(row, kg);
        cp_async16(sdst + so, (const char*)(base + (size_t)(bm + row) * K) + kg * 16 + koff);
    }
    // B: BN*16 slots (2 tiles x BN rows x 8 kg)
    #pragma unroll
    for (int i = 0; i < BN / 16; i++) {
        const int id = i * 256 + t;
        const int ishi = (id < BN * 8);
        const int idm = ishi ? id : id - BN * 8;
        const int row = idm >> 3, kg = idm & 7;
        const __nv_bfloat16* base = ishi ? Bh : Bl;
        const uint32_t so = 2 * GA3 + (ishi ? 0 : GB) + sw128(row, kg);
        cp_async16(sdst + so, (const char*)(base + (size_t)(bn + row) * K) + kg * 16 + koff);
    }
    cp_commit();
}

template <int MODE, int QSCALE, int BN>
__global__ __launch_bounds__(256, 2)
void gemm_mma(const __nv_bfloat16* __restrict__ Ah, const __nv_bfloat16* __restrict__ Al,
              const __nv_bfloat16* __restrict__ Bh, const __nv_bfloat16* __restrict__ Bl,
              const float* __restrict__ bias, float* __restrict__ C,
              __nv_bfloat16* __restrict__ Chi, __nv_bfloat16* __restrict__ Clo,
              int N, int K)
{
    constexpr int GB = BN * 128;             // B tile bytes
    constexpr int GSTAGE = 2 * GA3 + 2 * GB; // one stage
    constexpr int NTW = BN / 16;             // n-tiles per warp (width 8)
    constexpr int NP = NTW / 2;              // x4 b-frag loads per ks

    extern __shared__ char smem[];
    const uint32_t sb = smem_u32(smem);
    const int t = threadIdx.x;
    const int wid = t >> 5;
    const int lane = t & 31;
    const int bm = blockIdx.y * 128;
    const int bn = blockIdx.x * BN;
    const int wm = (wid >> 1) * 32;
    const int wn = (wid & 1) * (BN / 2);

    float acc[2][NTW][4];
    #pragma unroll
    for (int mt = 0; mt < 2; mt++)
        #pragma unroll
        for (int nt = 0; nt < NTW; nt++)
            #pragma unroll
            for (int j = 0; j < 4; j++) acc[mt][nt][j] = 0.f;

    const int niter = K >> 6;

    gemm_issue<BN>(sb, Ah, Al, Bh, Bl, bm, bn, K, t, 0);

    for (int c = 0; c < niter; c++) {
        if (c + 1 < niter) {
            gemm_issue<BN>(sb + ((c + 1) & 1) * GSTAGE, Ah, Al, Bh, Bl, bm, bn, K, t, c + 1);
            CP_WAIT(1);
        } else {
            CP_WAIT(0);
        }
        __syncthreads();

        const uint32_t stage = sb + (c & 1) * GSTAGE;
        #pragma unroll
        for (int ks = 0; ks < 4; ks++) {
            uint32_t ah[2][4], al[2][4], bh[NP][4], bl[NP][4];
            #pragma unroll
            for (int mt = 0; mt < 2; mt++) {
                uint32_t off = sw128(wm + mt * 16 + (lane & 15), ks * 2 + (lane >> 4));
                ldm_x4(ah[mt], stage + off);
                ldm_x4(al[mt], stage + GA3 + off);
            }
            #pragma unroll
            for (int p = 0; p < NP; p++) {
                uint32_t off = sw128(wn + (p * 2 + (lane >> 4)) * 8 + (lane & 7),
                                     ks * 2 + ((lane >> 3) & 1));
                ldm_x4(bh[p], stage + 2 * GA3 + off);
                ldm_x4(bl[p], stage + 2 * GA3 + GB + off);
            }
            #pragma unroll
            for (int mt = 0; mt < 2; mt++)
                #pragma unroll
                for (int nt = 0; nt < NTW; nt++) {
                    const uint32_t* bhf = &bh[nt >> 1][(nt & 1) * 2];
                    const uint32_t* blf = &bl[nt >> 1][(nt & 1) * 2];
                    mma16816(acc[mt][nt], ah[mt], bhf);
                    mma16816(acc[mt][nt], ah[mt], blf);
                    mma16816(acc[mt][nt], al[mt], bhf);
                }
        }
        __syncthreads();
    }

    // epilogue
    #pragma unroll
    for (int mt = 0; mt < 2; mt++) {
        const int r0 = bm + wm + mt * 16 + (lane >> 2);
        #pragma unroll
        for (int nt = 0; nt < NTW; nt++) {
            const int col = bn + wn + nt * 8 + (lane & 3) * 2;
            const float b0 = bias[col], b1 = bias[col + 1];
            float v00 = acc[mt][nt][0] + b0, v01 = acc[mt][nt][1] + b1;
            float v10 = acc[mt][nt][2] + b0, v11 = acc[mt][nt][3] + b1;
            if (MODE == 0) {
                *(float2*)&C[(size_t)r0 * N + col] = make_float2(v00, v01);
                *(float2*)&C[(size_t)(r0 + 8) * N + col] = make_float2(v10, v11);
            } else {
                if (QSCALE) {
                    const float qs = ((col % 192) < 64) ? 0.125f : 1.0f;
                    v00 *= qs; v01 *= qs; v10 *= qs; v11 *= qs;
                }
                __nv_bfloat16 h00 = __float2bfloat16_rn(v00);
                __nv_bfloat16 h01 = __float2bfloat16_rn(v01);
                __nv_bfloat16 h10 = __float2bfloat16_rn(v10);
                __nv_bfloat16 h11 = __float2bfloat16_rn(v11);
                *(uint32_t*)&Chi[(size_t)r0 * N + col] = pkh(h00, h01);
                *(uint32_t*)&Chi[(size_t)(r0 + 8) * N + col] = pkh(h10, h11);
                *(uint32_t*)&Clo[(size_t)r0 * N + col] =
                    pk2(v00 - __bfloat162float(h00), v01 - __bfloat162float(h01));
                *(uint32_t*)&Clo[(size_t)(r0 + 8) * N + col] =
                    pk2(v10 - __bfloat162float(h10), v11 - __bfloat162float(h11));
            }
        }
    }
}

// ---------------------------------------------------------------------------
// HMMA flash attention (R5-proven config): 4 warps, 64 q-rows/CTA, 2 CTAs/SM.
// smem: Qh Ql + 2 stages{Kh Kl Vh Vl}. Q pre-scaled by 1/sqrt(D) upstream.
// ---------------------------------------------------------------------------
#define AT      8192
#define ASTAGE  (4 * AT)
#define ASMEM   (2 * AT + 2 * ASTAGE)   // 81920

__device__ __forceinline__ void attn_issue_kv(uint32_t sdst, int b, int h, int kt, int t)
{
    const size_t base_off = ((size_t)(b * S_ + kt * 64) * TE_ + h * (3 * D_)) * 2;
    #pragma unroll
    for (int i = 0; i < 16; i++) {
        const int tile = i >> 2;                  // 0:Kh 1:Kl 2:Vh 3:Vl
        const int row = (i & 3) * 16 + (t >> 3);
        const int kg = t & 7;
        const __nv_bfloat16* arr = (tile & 1) ? g_qkv_lo : g_qkv_hi;
        const size_t go = base_off + (size_t)row * (TE_ * 2)
                        + (tile < 2 ? D_ : 2 * D_) * 2 + kg * 16;
        cp_async16(sdst + (uint32_t)tile * AT + sw128(row, kg), (const char*)arr + go);
    }
    cp_commit();
}

__global__ __launch_bounds__(128, 2)
void flash_mma()
{
    extern __shared__ char smem[];
    const uint32_t sb = smem_u32(smem);
    const uint32_t sQh = sb, sQl = sb + AT;

    const int t = threadIdx.x;
    const int wid = t >> 5;
    const int lane = t & 31;
    const int qt = blockIdx.x, h = blockIdx.y, b = blockIdx.z;

    {
        const size_t qbase = ((size_t)(b * S_ + qt * 64) * TE_ + h * (3 * D_)) * 2;
        #pragma unroll
        for (int i = 0; i < 8; i++) {
            const int tile = i >> 2;
            const int row = (i & 3) * 16 + (t >> 3);
            const int kg = t & 7;
            const __nv_bfloat16* arr = tile ? g_qkv_lo : g_qkv_hi;
            const size_t go = qbase + (size_t)row * (TE_ * 2) + kg * 16;
            cp_async16(sb + (uint32_t)tile * AT + sw128(row, kg), (const char*)arr + go);
        }
        cp_commit();
    }
    attn_issue_kv(sb + 2 * AT, b, h, 0, t);

    CP_WAIT(1);
    __syncthreads();

    uint32_t aqh[4][4], aql[4][4];
    #pragma unroll
    for (int ks = 0; ks < 4; ks++) {
        uint32_t off = sw128(wid * 16 + (lane & 15), ks * 2 + (lane >> 4));
        ldm_x4(aqh[ks], sQh + off);
        ldm_x4(aql[ks], sQl + off);
    }

    float o[8][4];
    #pragma unroll
    for (int nt = 0; nt < 8; nt++)
        #pragma unroll
        for (int j = 0; j < 4; j++) o[nt][j] = 0.f;
    float m0 = -1e30f, m1 = -1e30f, l0 = 0.f, l1 = 0.f;

    const int NT = S_ / 64;
    for (int kt = 0; kt < NT; kt++) {
        if (kt + 1 < NT) {
            attn_issue_kv(sb + 2 * AT + ((kt + 1) & 1) * ASTAGE, b, h, kt + 1, t);
            CP_WAIT(1);
        } else {
            CP_WAIT(0);
        }
        __syncthreads();

        const uint32_t st = sb + 2 * AT + (kt & 1) * ASTAGE;
        const uint32_t stKh = st, stKl = st + AT, stVh = st + 2 * AT, stVl = st + 3 * AT;

        // ---- S = Q K^T (3-term split, fp32 accum); Q pre-scaled ----
        float sc[8][4];
        #pragma unroll
        for (int nt = 0; nt < 8; nt++)
            #pragma unroll
            for (int j = 0; j < 4; j++) sc[nt][j] = 0.f;
        #pragma unroll
        for (int ks = 0; ks < 4; ks++) {
            #pragma unroll
            for (int p = 0; p < 4; p++) {
                uint32_t off = sw128((p * 2 + (lane >> 4)) * 8 + (lane & 7),
                                     ks * 2 + ((lane >> 3) & 1));
                uint32_t bh[4], bl[4];
                ldm_x4(bh, stKh + off);
                ldm_x4(bl, stKl + off);
                mma16816(sc[2 * p], aqh[ks], bh);
                mma16816(sc[2 * p], aqh[ks], bl);
                mma16816(sc[2 * p], aql[ks], bh);
                mma16816(sc[2 * p + 1], aqh[ks], bh + 2);
                mma16816(sc[2 * p + 1], aqh[ks], bl + 2);
                mma16816(sc[2 * p + 1], aql[ks], bh + 2);
            }
        }

        // ---- online softmax ----
        float rx0 = -1e30f, rx1 = -1e30f;
        #pragma unroll
        for (int nt = 0; nt < 8; nt++) {
            rx0 = fmaxf(rx0, fmaxf(sc[nt][0], sc[nt][1]));
            rx1 = fmaxf(rx1, fmaxf(sc[nt][2], sc[nt][3]));
        }
        rx0 = fmaxf(rx0, __shfl_xor_sync(0xffffffffu, rx0, 1));
        rx0 = fmaxf(rx0, __shfl_xor_sync(0xffffffffu, rx0, 2));
        rx1 = fmaxf(rx1, __shfl_xor_sync(0xffffffffu, rx1, 1));
        rx1 = fmaxf(rx1, __shfl_xor_sync(0xffffffffu, rx1, 2));

        const float mn0 = fmaxf(m0, rx0), mn1 = fmaxf(m1, rx1);
        const float s0 = __expf(m0 - mn0), s1 = __expf(m1 - mn1);
        m0 = mn0; m1 = mn1;
        #pragma unroll
        for (int nt = 0; nt < 8; nt++) {
            o[nt][0] *= s0; o[nt][1] *= s0;
            o[nt][2] *= s1; o[nt][3] *= s1;
        }
        float sum0 = 0.f, sum1 = 0.f;
        #pragma unroll
        for (int nt = 0; nt < 8; nt++) {
            sc[nt][0] = __expf(sc[nt][0] - mn0);
            sc[nt][1] = __expf(sc[nt][1] - mn0);
            sc[nt][2] = __expf(sc[nt][2] - mn1);
            sc[nt][3] = __expf(sc[nt][3] - mn1);
            sum0 += sc[nt][0] + sc[nt][1];
            sum1 += sc[nt][2] + sc[nt][3];
        }
        sum0 += __shfl_xor_sync(0xffffffffu, sum0, 1);
        sum0 += __shfl_xor_sync(0xffffffffu, sum0, 2);
        sum1 += __shfl_xor_sync(0xffffffffu, sum1, 1);
        sum1 += __shfl_xor_sync(0xffffffffu, sum1, 2);
        l0 = l0 * s0 + sum0;
        l1 = l1 * s1 + sum1;

        // ---- O += P V (3-term split) ----
        #pragma unroll
        for (int ks = 0; ks < 4; ks++) {
            uint32_t aph[4], apl[4];
            {
                const int j0 = 2 * ks, j1 = 2 * ks + 1;
                __nv_bfloat16 h00 = __float2bfloat16_rn(sc[j0][0]);
                __nv_bfloat16 h01 = __float2bfloat16_rn(sc[j0][1]);
                __nv_bfloat16 h02 = __float2bfloat16_rn(sc[j0][2]);
                __nv_bfloat16 h03 = __float2bfloat16_rn(sc[j0][3]);
                __nv_bfloat16 h10 = __float2bfloat16_rn(sc[j1][0]);
                __nv_bfloat16 h11 = __float2bfloat16_rn(sc[j1][1]);
                __nv_bfloat16 h12 = __float2bfloat16_rn(sc[j1][2]);
                __nv_bfloat16 h13 = __float2bfloat16_rn(sc[j1][3]);
                aph[0] = pkh(h00, h01);
                aph[1] = pkh(h02, h03);
                aph[2] = pkh(h10, h11);
                aph[3] = pkh(h12, h13);
                apl[0] = pk2(sc[j0][0] - __bfloat162float(h00), sc[j0][1] - __bfloat162float(h01));
                apl[1] = pk2(sc[j0][2] - __bfloat162float(h02), sc[j0][3] - __bfloat162float(h03));
                apl[2] = pk2(sc[j1][0] - __bfloat162float(h10), sc[j1][1] - __bfloat162float(h11));
                apl[3] = pk2(sc[j1][2] - __bfloat162float(h12), sc[j1][3] - __bfloat162float(h13));
            }
            #pragma unroll
            for (int p = 0; p < 4; p++) {
                uint32_t off = sw128(ks * 16 + (lane & 15), 2 * p + (lane >> 4));
                uint32_t bh[4], bl[4];
                ldm_x4t(bh, stVh + off);
                ldm_x4t(bl, stVl + off);
                mma16816(o[2 * p], aph, bh);
                mma16816(o[2 * p], aph, bl);
                mma16816(o[2 * p], apl, bh);
                mma16816(o[2 * p + 1], aph, bh + 2);
                mma16816(o[2 * p + 1], aph, bl + 2);
                mma16816(o[2 * p + 1], apl, bh + 2);
            }
        }
        __syncthreads();
    }

    // ---- normalize, split hi/lo, store ----
    const float inv0 = 1.f / l0, inv1 = 1.f / l1;
    const int r0 = b * S_ + qt * 64 + wid * 16 + (lane >> 2);
    #pragma unroll
    for (int nt = 0; nt < 8; nt++) {
        const int col = h * D_ + nt * 8 + (lane & 3) * 2;
        float v00 = o[nt][0] * inv0, v01 = o[nt][1] * inv0;
        float v10 = o[nt][2] * inv1, v11 = o[nt][3] * inv1;
        __nv_bfloat16 h00 = __float2bfloat16_rn(v00);
        __nv_bfloat16 h01 = __float2bfloat16_rn(v01);
        __nv_bfloat16 h10 = __float2bfloat16_rn(v10);
        __nv_bfloat16 h11 = __float2bfloat16_rn(v11);
        *(uint32_t*)&g_o_hi[(size_t)r0 * E_ + col] = pkh(h00, h01);
        *(uint32_t*)&g_o_hi[(size_t)(r0 + 8) * E_ + col] = pkh(h10, h11);
        *(uint32_t*)&g_o_lo[(size_t)r0 * E_ + col] =
            pk2(v00 - __bfloat162float(h00), v01 - __bfloat162float(h01));
        *(uint32_t*)&g_o_lo[(size_t)(r0 + 8) * E_ + col] =
            pk2(v10 - __bfloat162float(h10), v11 - __bfloat162float(h11));
    }
}

// ---------------------------------------------------------------------------
// Launch
// ---------------------------------------------------------------------------
extern "C" void kernel_launch(void* const* d_in, const int* in_sizes, int n_in,
                              void* d_out, int out_size)
{
    const float* x     = (const float*)d_in[0];
    const float* w_qkv = (const float*)d_in[1];
    const float* b_qkv = (const float*)d_in[2];
    const float* w_o   = (const float*)d_in[3];
    const float* b_o   = (const float*)d_in[4];
    float* out = (float*)d_out;

    __nv_bfloat16 *qkv_hi, *qkv_lo, *o_hi, *o_lo;
    __nv_bfloat16 *x_hi, *x_lo, *wq_hi, *wq_lo, *wo_hi, *wo_lo;
    cudaGetSymbolAddress((void**)&qkv_hi, g_qkv_hi);
    cudaGetSymbolAddress((void**)&qkv_lo, g_qkv_lo);
    cudaGetSymbolAddress((void**)&o_hi, g_o_hi);
    cudaGetSymbolAddress((void**)&o_lo, g_o_lo);
    cudaGetSymbolAddress((void**)&x_hi, g_x_hi);
    cudaGetSymbolAddress((void**)&x_lo, g_x_lo);
    cudaGetSymbolAddress((void**)&wq_hi, g_wq_hi);
    cudaGetSymbolAddress((void**)&wq_lo, g_wq_lo);
    cudaGetSymbolAddress((void**)&wo_hi, g_wo_hi);
    cudaGetSymbolAddress((void**)&wo_lo, g_wo_lo);

    constexpr int GSMEM_96 = 2 * (2 * GA3 + 2 * 96 * 128);   // 114688
    constexpr int GSMEM_64 = 2 * (2 * GA3 + 2 * 64 * 128);   // 98304

    cudaFuncSetAttribute((void*)gemm_mma<1,1,96>, cudaFuncAttributeMaxDynamicSharedMemorySize, GSMEM_96);
    cudaFuncSetAttribute((void*)gemm_mma<0,0,64>, cudaFuncAttributeMaxDynamicSharedMemorySize, GSMEM_64);
    cudaFuncSetAttribute((void*)flash_mma, cudaFuncAttributeMaxDynamicSharedMemorySize, ASMEM);

    {
        int n4 = (MTOT * E_) / 4;
        split_bf16x2<<<(n4 + 255) / 256, 256>>>(x, x_hi, x_lo, n4);
        n4 = (TE_ * E_) / 4;
        split_bf16x2<<<(n4 + 255) / 256, 256>>>(w_qkv, wq_hi, wq_lo, n4);
        n4 = (E_ * E_) / 4;
        split_bf16x2<<<(n4 + 255) / 256, 256>>>(w_o, wo_hi, wo_lo, n4);
    }

    {
        dim3 g(TE_ / 96, MTOT / 128);    // 32 x 32
        gemm_mma<1,1,96><<<g, 256, GSMEM_96>>>(x_hi, x_lo, wq_hi, wq_lo, b_qkv,
                                               nullptr, qkv_hi, qkv_lo, TE_, E_);
    }
    {
        dim3 g(S_ / 64, H_, B_);          // 32 x 16 x 2
        flash_mma<<<g, 128, ASMEM>>>();
    }
    {
        dim3 g(E_ / 64, MTOT / 128);      // 16 x 32
        gemm_mma<0,0,64><<<g, 256, GSMEM_64>>>(o_hi, o_lo, wo_hi, wo_lo, b_o,
                                               out, nullptr, nullptr, E_, E_);
    }
}

// round 10
// speedup vs baseline: 1.7295x; 1.0294x over previous
#include <cuda_runtime.h>
#include <cuda_bf16.h>
#include <cstdint>

#define B_   2
#define S_   2048
#define H_   16
#define D_   64
#define E_   1024
#define TE_  3072
#define MTOT (B_ * S_)   // 4096

// ---------------------------------------------------------------------------
// Scratch (__device__ globals; no allocation allowed)
// ---------------------------------------------------------------------------
__device__ __nv_bfloat16 g_qkv_hi[(size_t)MTOT * TE_];
__device__ __nv_bfloat16 g_qkv_lo[(size_t)MTOT * TE_];
__device__ __nv_bfloat16 g_o_hi[(size_t)MTOT * E_];
__device__ __nv_bfloat16 g_o_lo[(size_t)MTOT * E_];
__device__ __nv_bfloat16 g_x_hi[(size_t)MTOT * E_];
__device__ __nv_bfloat16 g_x_lo[(size_t)MTOT * E_];
__device__ __nv_bfloat16 g_wq_hi[(size_t)TE_ * E_];
__device__ __nv_bfloat16 g_wq_lo[(size_t)TE_ * E_];
__device__ __nv_bfloat16 g_wo_hi[(size_t)E_ * E_];
__device__ __nv_bfloat16 g_wo_lo[(size_t)E_ * E_];

// ---------------------------------------------------------------------------
// Helpers (sm_80-level PTX only)
// ---------------------------------------------------------------------------
__device__ __forceinline__ uint32_t smem_u32(const void* p) {
    uint32_t a;
    asm("{ .reg .u64 t; cvta.to.shared.u64 t, %1; cvt.u32.u64 %0, t; }" : "=r"(a) : "l"(p));
    return a;
}
__device__ __forceinline__ uint32_t pk2(float a, float b) {
    __nv_bfloat162 t = __floats2bfloat162_rn(a, b);
    return *reinterpret_cast<uint32_t*>(&t);
}
__device__ __forceinline__ uint32_t pkh(__nv_bfloat16 a, __nv_bfloat16 b) {
    __nv_bfloat162 t(a, b);
    return *reinterpret_cast<uint32_t*>(&t);
}
__device__ __forceinline__ void ldm_x4(uint32_t* r, uint32_t addr) {
    asm volatile("ldmatrix.sync.aligned.m8n8.x4.shared.b16 {%0,%1,%2,%3}, [%4];"
                 : "=r"(r[0]), "=r"(r[1]), "=r"(r[2]), "=r"(r[3]) : "r"(addr));
}
__device__ __forceinline__ void ldm_x4t(uint32_t* r, uint32_t addr) {
    asm volatile("ldmatrix.sync.aligned.m8n8.x4.trans.shared.b16 {%0,%1,%2,%3}, [%4];"
                 : "=r"(r[0]), "=r"(r[1]), "=r"(r[2]), "=r"(r[3]) : "r"(addr));
}
__device__ __forceinline__ void mma16816(float* c, const uint32_t* a, const uint32_t* b) {
    asm volatile(
        "mma.sync.aligned.m16n8k16.row.col.f32.bf16.bf16.f32 "
        "{%0,%1,%2,%3}, {%4,%5,%6,%7}, {%8,%9}, {%0,%1,%2,%3};"
        : "+f"(c[0]), "+f"(c[1]), "+f"(c[2]), "+f"(c[3])
        : "r"(a[0]), "r"(a[1]), "r"(a[2]), "r"(a[3]), "r"(b[0]), "r"(b[1]));
}
__device__ __forceinline__ void cp_async16(uint32_t saddr, const void* gaddr) {
    asm volatile("cp.async.cg.shared.global [%0], [%1], 16;" :: "r"(saddr), "l"(gaddr) : "memory");
}
__device__ __forceinline__ void cp_commit() {
    asm volatile("cp.async.commit_group;" ::: "memory");
}
#define CP_WAIT(n) asm volatile("cp.async.wait_group %0;" :: "n"(n) : "memory")

// 128B-row XOR swizzle (8x16B groups), conflict-free for ldmatrix
__device__ __forceinline__ uint32_t sw128(uint32_t row, uint32_t kg) {
    return row * 128u + ((kg ^ (row & 7u)) << 4);
}

// ---------------------------------------------------------------------------
// Fused fp32 -> bf16 hi/lo split for x, w_qkv, w_o in ONE launch
// ---------------------------------------------------------------------------
__device__ __forceinline__ void split_one(const float* in, __nv_bfloat16* hi,
                                          __nv_bfloat16* lo, int i)
{
    float4 v = ((const float4*)in)[i];
    __nv_bfloat16 h0 = __float2bfloat16_rn(v.x);
    __nv_bfloat16 h1 = __float2bfloat16_rn(v.y);
    __nv_bfloat16 h2 = __float2bfloat16_rn(v.z);
    __nv_bfloat16 h3 = __float2bfloat16_rn(v.w);
    uint2 hp = make_uint2(pkh(h0, h1), pkh(h2, h3));
    uint2 lp = make_uint2(pk2(v.x - __bfloat162float(h0), v.y - __bfloat162float(h1)),
                          pk2(v.z - __bfloat162float(h2), v.w - __bfloat162float(h3)));
    *(uint2*)(hi + (size_t)i * 4) = hp;
    *(uint2*)(lo + (size_t)i * 4) = lp;
}

#define N4_X  ((MTOT * E_) / 4)   // 1048576
#define N4_WQ ((TE_ * E_) / 4)    // 786432
#define N4_WO ((E_ * E_) / 4)     // 262144

__global__ __launch_bounds__(256)
void split_all(const float* __restrict__ x, const float* __restrict__ wq,
               const float* __restrict__ wo)
{
    int i = blockIdx.x * blockDim.x + threadIdx.x;
    if (i < N4_X) {
        split_one(x, g_x_hi, g_x_lo, i);
    } else if (i < N4_X + N4_WQ) {
        split_one(wq, g_wq_hi, g_wq_lo, i - N4_X);
    } else if (i < N4_X + N4_WQ + N4_WO) {
        split_one(wo, g_wo_hi, g_wo_lo, i - N4_X - N4_WQ);
    }
}

// ---------------------------------------------------------------------------
// HMMA split-bf16 GEMM (NT): C = A[M,K]*B[N,K]^T + bias  (proven R8 config)
// 128xBN block tile (BN = 64 or 96), 8 warps, BK=64, 2-stage cp.async, 2 CTAs/SM.
// ---------------------------------------------------------------------------
#define GA3 16384                     // A tile: 128 rows x 128B

template <int BN>
__device__ __forceinline__ void gemm_issue(
    uint32_t sdst, const __nv_bfloat16* Ah, const __nv_bfloat16* Al,
    const __nv_bfloat16* Bh, const __nv_bfloat16* Bl,
    int bm, int bn, int K, int t, int c)
{
    const int GB = BN * 128;
    const int koff = c * 128;
    #pragma unroll
    for (int i = 0; i < 8; i++) {
        const int id = i * 256 + t;
        const int idm = id & 1023;
        const int row = idm >> 3, kg = idm & 7;
        const __nv_bfloat16* base = (id >> 10) ? Al : Ah;
        const uint32_t so = ((id >> 10) ? GA3 : 0) + sw128(row, kg);
        cp_async16(sdst + so, (const char*)(base + (size_t)(bm + row) * K) + kg * 16 + koff);
    }
    #pragma unroll
    for (int i = 0; i < BN / 16; i++) {
        const int id = i * 256 + t;
        const int ishi = (id < BN * 8);
        const int idm = ishi ? id : id - BN * 8;
        const int row = idm >> 3, kg = idm & 7;
        const __nv_bfloat16* base = ishi ? Bh : Bl;
        const uint32_t so = 2 * GA3 + (ishi ? 0 : GB) + sw128(row, kg);
        cp_async16(sdst + so, (const char*)(base + (size_t)(bn + row) * K) + kg * 16 + koff);
    }
    cp_commit();
}

template <int MODE, int QSCALE, int BN>
__global__ __launch_bounds__(256, 2)
void gemm_mma(const __nv_bfloat16* __restrict__ Ah, const __nv_bfloat16* __restrict__ Al,
              const __nv_bfloat16* __restrict__ Bh, const __nv_bfloat16* __restrict__ Bl,
              const float* __restrict__ bias, float* __restrict__ C,
              __nv_bfloat16* __restrict__ Chi, __nv_bfloat16* __restrict__ Clo,
              int N, int K)
{
    constexpr int GB = BN * 128;
    constexpr int GSTAGE = 2 * GA3 + 2 * GB;
    constexpr int NTW = BN / 16;
    constexpr int NP = NTW / 2;

    extern __shared__ char smem[];
    const uint32_t sb = smem_u32(smem);
    const int t = threadIdx.x;
    const int wid = t >> 5;
    const int lane = t & 31;
    const int bm = blockIdx.y * 128;
    const int bn = blockIdx.x * BN;
    const int wm = (wid >> 1) * 32;
    const int wn = (wid & 1) * (BN / 2);

    float acc[2][NTW][4];
    #pragma unroll
    for (int mt = 0; mt < 2; mt++)
        #pragma unroll
        for (int nt = 0; nt < NTW; nt++)
            #pragma unroll
            for (int j = 0; j < 4; j++) acc[mt][nt][j] = 0.f;

    const int niter = K >> 6;

    gemm_issue<BN>(sb, Ah, Al, Bh, Bl, bm, bn, K, t, 0);

    for (int c = 0; c < niter; c++) {
        if (c + 1 < niter) {
            gemm_issue<BN>(sb + ((c + 1) & 1) * GSTAGE, Ah, Al, Bh, Bl, bm, bn, K, t, c + 1);
            CP_WAIT(1);
        } else {
            CP_WAIT(0);
        }
        __syncthreads();

        const uint32_t stage = sb + (c & 1) * GSTAGE;
        #pragma unroll
        for (int ks = 0; ks < 4; ks++) {
            uint32_t ah[2][4], al[2][4], bh[NP][4], bl[NP][4];
            #pragma unroll
            for (int mt = 0; mt < 2; mt++) {
                uint32_t off = sw128(wm + mt * 16 + (lane & 15), ks * 2 + (lane >> 4));
                ldm_x4(ah[mt], stage + off);
                ldm_x4(al[mt], stage + GA3 + off);
            }
            #pragma unroll
            for (int p = 0; p < NP; p++) {
                uint32_t off = sw128(wn + (p * 2 + (lane >> 4)) * 8 + (lane & 7),
                                     ks * 2 + ((lane >> 3) & 1));
                ldm_x4(bh[p], stage + 2 * GA3 + off);
                ldm_x4(bl[p], stage + 2 * GA3 + GB + off);
            }
            #pragma unroll
            for (int mt = 0; mt < 2; mt++)
                #pragma unroll
                for (int nt = 0; nt < NTW; nt++) {
                    const uint32_t* bhf = &bh[nt >> 1][(nt & 1) * 2];
                    const uint32_t* blf = &bl[nt >> 1][(nt & 1) * 2];
                    mma16816(acc[mt][nt], ah[mt], bhf);
                    mma16816(acc[mt][nt], ah[mt], blf);
                    mma16816(acc[mt][nt], al[mt], bhf);
                }
        }
        __syncthreads();
    }

    #pragma unroll
    for (int mt = 0; mt < 2; mt++) {
        const int r0 = bm + wm + mt * 16 + (lane >> 2);
        #pragma unroll
        for (int nt = 0; nt < NTW; nt++) {
            const int col = bn + wn + nt * 8 + (lane & 3) * 2;
            const float b0 = bias[col], b1 = bias[col + 1];
            float v00 = acc[mt][nt][0] + b0, v01 = acc[mt][nt][1] + b1;
            float v10 = acc[mt][nt][2] + b0, v11 = acc[mt][nt][3] + b1;
            if (MODE == 0) {
                *(float2*)&C[(size_t)r0 * N + col] = make_float2(v00, v01);
                *(float2*)&C[(size_t)(r0 + 8) * N + col] = make_float2(v10, v11);
            } else {
                if (QSCALE) {
                    const float qs = ((col % 192) < 64) ? 0.125f : 1.0f;
                    v00 *= qs; v01 *= qs; v10 *= qs; v11 *= qs;
                }
                __nv_bfloat16 h00 = __float2bfloat16_rn(v00);
                __nv_bfloat16 h01 = __float2bfloat16_rn(v01);
                __nv_bfloat16 h10 = __float2bfloat16_rn(v10);
                __nv_bfloat16 h11 = __float2bfloat16_rn(v11);
                *(uint32_t*)&Chi[(size_t)r0 * N + col] = pkh(h00, h01);
                *(uint32_t*)&Chi[(size_t)(r0 + 8) * N + col] = pkh(h10, h11);
                *(uint32_t*)&Clo[(size_t)r0 * N + col] =
                    pk2(v00 - __bfloat162float(h00), v01 - __bfloat162float(h01));
                *(uint32_t*)&Clo[(size_t)(r0 + 8) * N + col] =
                    pk2(v10 - __bfloat162float(h10), v11 - __bfloat162float(h11));
            }
        }
    }
}

// ---------------------------------------------------------------------------
// HMMA flash attention: 4 warps, 64 q-rows/CTA, 3 CTAs/SM.
// smem = just 2 KV stages (64KB); Q parks in stage 1 during prologue, then
// lives in registers. Q pre-scaled by 1/sqrt(D) upstream.
// ---------------------------------------------------------------------------
#define AT      8192
#define ASTAGE  (4 * AT)
#define ASMEM   (2 * ASTAGE)   // 65536

__device__ __forceinline__ void attn_issue_kv(uint32_t sdst, int b, int h, int kt, int t)
{
    const size_t base_off = ((size_t)(b * S_ + kt * 64) * TE_ + h * (3 * D_)) * 2;
    #pragma unroll
    for (int i = 0; i < 16; i++) {
        const int tile = i >> 2;                  // 0:Kh 1:Kl 2:Vh 3:Vl
        const int row = (i & 3) * 16 + (t >> 3);
        const int kg = t & 7;
        const __nv_bfloat16* arr = (tile & 1) ? g_qkv_lo : g_qkv_hi;
        const size_t go = base_off + (size_t)row * (TE_ * 2)
                        + (tile < 2 ? D_ : 2 * D_) * 2 + kg * 16;
        cp_async16(sdst + (uint32_t)tile * AT + sw128(row, kg), (const char*)arr + go);
    }
    cp_commit();
}

__global__ __launch_bounds__(128, 3)
void flash_mma()
{
    extern __shared__ char smem[];
    const uint32_t sb = smem_u32(smem);

    const int t = threadIdx.x;
    const int wid = t >> 5;
    const int lane = t & 31;
    const int qt = blockIdx.x, h = blockIdx.y, b = blockIdx.z;

    // prologue: Q -> stage-1 slots (Kh,Kl positions); KV(0) -> stage 0
    {
        const size_t qbase = ((size_t)(b * S_ + qt * 64) * TE_ + h * (3 * D_)) * 2;
        #pragma unroll
        for (int i = 0; i < 8; i++) {
            const int tile = i >> 2;              // 0:Qh 1:Ql
            const int row = (i & 3) * 16 + (t >> 3);
            const int kg = t & 7;
            const __nv_bfloat16* arr = tile ? g_qkv_lo : g_qkv_hi;
            const size_t go = qbase + (size_t)row * (TE_ * 2) + kg * 16;
            cp_async16(sb + ASTAGE + (uint32_t)tile * AT + sw128(row, kg),
                       (const char*)arr + go);
        }
        cp_commit();   // G0 = Q
    }
    attn_issue_kv(sb, b, h, 0, t);   // G1 = KV(0)

    CP_WAIT(1);        // Q landed
    __syncthreads();

    uint32_t aqh[4][4], aql[4][4];
    #pragma unroll
    for (int ks = 0; ks < 4; ks++) {
        uint32_t off = sw128(wid * 16 + (lane & 15), ks * 2 + (lane >> 4));
        ldm_x4(aqh[ks], sb + ASTAGE + off);
        ldm_x4(aql[ks], sb + ASTAGE + AT + off);
    }
    __syncthreads();   // Q frags read before stage-1 is overwritten by KV(1)

    float o[8][4];
    #pragma unroll
    for (int nt = 0; nt < 8; nt++)
        #pragma unroll
        for (int j = 0; j < 4; j++) o[nt][j] = 0.f;
    float m0 = -1e30f, m1 = -1e30f, l0 = 0.f, l1 = 0.f;

    const int NT = S_ / 64;
    for (int kt = 0; kt < NT; kt++) {
        if (kt + 1 < NT) {
            attn_issue_kv(sb + ((kt + 1) & 1) * ASTAGE, b, h, kt + 1, t);
            CP_WAIT(1);
        } else {
            CP_WAIT(0);
        }
        __syncthreads();

        const uint32_t st = sb + (kt & 1) * ASTAGE;
        const uint32_t stKh = st, stKl = st + AT, stVh = st + 2 * AT, stVl = st + 3 * AT;

        // ---- S = Q K^T (3-term split, fp32 accum); Q pre-scaled ----
        float sc[8][4];
        #pragma unroll
        for (int nt = 0; nt < 8; nt++)
            #pragma unroll
            for (int j = 0; j < 4; j++) sc[nt][j] = 0.f;
        #pragma unroll
        for (int ks = 0; ks < 4; ks++) {
            #pragma unroll
            for (int p = 0; p < 4; p++) {
                uint32_t off = sw128((p * 2 + (lane >> 4)) * 8 + (lane & 7),
                                     ks * 2 + ((lane >> 3) & 1));
                uint32_t bh[4], bl[4];
                ldm_x4(bh, stKh + off);
                ldm_x4(bl, stKl + off);
                mma16816(sc[2 * p], aqh[ks], bh);
                mma16816(sc[2 * p], aqh[ks], bl);
                mma16816(sc[2 * p], aql[ks], bh);
                mma16816(sc[2 * p + 1], aqh[ks], bh + 2);
                mma16816(sc[2 * p + 1], aqh[ks], bl + 2);
                mma16816(sc[2 * p + 1], aql[ks], bh + 2);
            }
        }

        // ---- online softmax ----
        float rx0 = -1e30f, rx1 = -1e30f;
        #pragma unroll
        for (int nt = 0; nt < 8; nt++) {
            rx0 = fmaxf(rx0, fmaxf(sc[nt][0], sc[nt][1]));
            rx1 = fmaxf(rx1, fmaxf(sc[nt][2], sc[nt][3]));
        }
        rx0 = fmaxf(rx0, __shfl_xor_sync(0xffffffffu, rx0, 1));
        rx0 = fmaxf(rx0, __shfl_xor_sync(0xffffffffu, rx0, 2));
        rx1 = fmaxf(rx1, __shfl_xor_sync(0xffffffffu, rx1, 1));
        rx1 = fmaxf(rx1, __shfl_xor_sync(0xffffffffu, rx1, 2));

        const float mn0 = fmaxf(m0, rx0), mn1 = fmaxf(m1, rx1);
        const float s0 = __expf(m0 - mn0), s1 = __expf(m1 - mn1);
        m0 = mn0; m1 = mn1;
        #pragma unroll
        for (int nt = 0; nt < 8; nt++) {
            o[nt][0] *= s0; o[nt][1] *= s0;
            o[nt][2] *= s1; o[nt][3] *= s1;
        }
        float sum0 = 0.f, sum1 = 0.f;
        #pragma unroll
        for (int nt = 0; nt < 8; nt++) {
            sc[nt][0] = __expf(sc[nt][0] - mn0);
            sc[nt][1] = __expf(sc[nt][1] - mn0);
            sc[nt][2] = __expf(sc[nt][2] - mn1);
            sc[nt][3] = __expf(sc[nt][3] - mn1);
            sum0 += sc[nt][0] + sc[nt][1];
            sum1 += sc[nt][2] + sc[nt][3];
        }
        sum0 += __shfl_xor_sync(0xffffffffu, sum0, 1);
        sum0 += __shfl_xor_sync(0xffffffffu, sum0, 2);
        sum1 += __shfl_xor_sync(0xffffffffu, sum1, 1);
        sum1 += __shfl_xor_sync(0xffffffffu, sum1, 2);
        l0 = l0 * s0 + sum0;
        l1 = l1 * s1 + sum1;

        // ---- O += P V (3-term split) ----
        #pragma unroll
        for (int ks = 0; ks < 4; ks++) {
            uint32_t aph[4], apl[4];
            {
                const int j0 = 2 * ks, j1 = 2 * ks + 1;
                __nv_bfloat16 h00 = __float2bfloat16_rn(sc[j0][0]);
                __nv_bfloat16 h01 = __float2bfloat16_rn(sc[j0][1]);
                __nv_bfloat16 h02 = __float2bfloat16_rn(sc[j0][2]);
                __nv_bfloat16 h03 = __float2bfloat16_rn(sc[j0][3]);
                __nv_bfloat16 h10 = __float2bfloat16_rn(sc[j1][0]);
                __nv_bfloat16 h11 = __float2bfloat16_rn(sc[j1][1]);
                __nv_bfloat16 h12 = __float2bfloat16_rn(sc[j1][2]);
                __nv_bfloat16 h13 = __float2bfloat16_rn(sc[j1][3]);
                aph[0] = pkh(h00, h01);
                aph[1] = pkh(h02, h03);
                aph[2] = pkh(h10, h11);
                aph[3] = pkh(h12, h13);
                apl[0] = pk2(sc[j0][0] - __bfloat162float(h00), sc[j0][1] - __bfloat162float(h01));
                apl[1] = pk2(sc[j0][2] - __bfloat162float(h02), sc[j0][3] - __bfloat162float(h03));
                apl[2] = pk2(sc[j1][0] - __bfloat162float(h10), sc[j1][1] - __bfloat162float(h11));
                apl[3] = pk2(sc[j1][2] - __bfloat162float(h12), sc[j1][3] - __bfloat162float(h13));
            }
            #pragma unroll
            for (int p = 0; p < 4; p++) {
                uint32_t off = sw128(ks * 16 + (lane & 15), 2 * p + (lane >> 4));
                uint32_t bh[4], bl[4];
                ldm_x4t(bh, stVh + off);
                ldm_x4t(bl, stVl + off);
                mma16816(o[2 * p], aph, bh);
                mma16816(o[2 * p], aph, bl);
                mma16816(o[2 * p], apl, bh);
                mma16816(o[2 * p + 1], aph, bh + 2);
                mma16816(o[2 * p + 1], aph, bl + 2);
                mma16816(o[2 * p + 1], apl, bh + 2);
            }
        }
        __syncthreads();
    }

    // ---- normalize, split hi/lo, store ----
    const float inv0 = 1.f / l0, inv1 = 1.f / l1;
    const int r0 = b * S_ + qt * 64 + wid * 16 + (lane >> 2);
    #pragma unroll
    for (int nt = 0; nt < 8; nt++) {
        const int col = h * D_ + nt * 8 + (lane & 3) * 2;
        float v00 = o[nt][0] * inv0, v01 = o[nt][1] * inv0;
        float v10 = o[nt][2] * inv1, v11 = o[nt][3] * inv1;
        __nv_bfloat16 h00 = __float2bfloat16_rn(v00);
        __nv_bfloat16 h01 = __float2bfloat16_rn(v01);
        __nv_bfloat16 h10 = __float2bfloat16_rn(v10);
        __nv_bfloat16 h11 = __float2bfloat16_rn(v11);
        *(uint32_t*)&g_o_hi[(size_t)r0 * E_ + col] = pkh(h00, h01);
        *(uint32_t*)&g_o_hi[(size_t)(r0 + 8) * E_ + col] = pkh(h10, h11);
        *(uint32_t*)&g_o_lo[(size_t)r0 * E_ + col] =
            pk2(v00 - __bfloat162float(h00), v01 - __bfloat162float(h01));
        *(uint32_t*)&g_o_lo[(size_t)(r0 + 8) * E_ + col] =
            pk2(v10 - __bfloat162float(h10), v11 - __bfloat162float(h11));
    }
}

// ---------------------------------------------------------------------------
// Launch
// ---------------------------------------------------------------------------
extern "C" void kernel_launch(void* const* d_in, const int* in_sizes, int n_in,
                              void* d_out, int out_size)
{
    const float* x     = (const float*)d_in[0];
    const float* w_qkv = (const float*)d_in[1];
    const float* b_qkv = (const float*)d_in[2];
    const float* w_o   = (const float*)d_in[3];
    const float* b_o   = (const float*)d_in[4];
    float* out = (float*)d_out;

    __nv_bfloat16 *qkv_hi, *qkv_lo, *o_hi, *o_lo;
    __nv_bfloat16 *x_hi, *x_lo, *wq_hi, *wq_lo, *wo_hi, *wo_lo;
    cudaGetSymbolAddress((void**)&qkv_hi, g_qkv_hi);
    cudaGetSymbolAddress((void**)&qkv_lo, g_qkv_lo);
    cudaGetSymbolAddress((void**)&o_hi, g_o_hi);
    cudaGetSymbolAddress((void**)&o_lo, g_o_lo);
    cudaGetSymbolAddress((void**)&x_hi, g_x_hi);
    cudaGetSymbolAddress((void**)&x_lo, g_x_lo);
    cudaGetSymbolAddress((void**)&wq_hi, g_wq_hi);
    cudaGetSymbolAddress((void**)&wq_lo, g_wq_lo);
    cudaGetSymbolAddress((void**)&wo_hi, g_wo_hi);
    cudaGetSymbolAddress((void**)&wo_lo, g_wo_lo);

    constexpr int GSMEM_96 = 2 * (2 * GA3 + 2 * 96 * 128);   // 114688
    constexpr int GSMEM_64 = 2 * (2 * GA3 + 2 * 64 * 128);   // 98304

    cudaFuncSetAttribute((void*)gemm_mma<1,1,96>, cudaFuncAttributeMaxDynamicSharedMemorySize, GSMEM_96);
    cudaFuncSetAttribute((void*)gemm_mma<0,0,64>, cudaFuncAttributeMaxDynamicSharedMemorySize, GSMEM_64);
    cudaFuncSetAttribute((void*)flash_mma, cudaFuncAttributeMaxDynamicSharedMemorySize, ASMEM);

    {
        const int total = N4_X + N4_WQ + N4_WO;
        split_all<<<(total + 255) / 256, 256>>>(x, w_qkv, w_o);
    }

    {
        dim3 g(TE_ / 96, MTOT / 128);    // 32 x 32
        gemm_mma<1,1,96><<<g, 256, GSMEM_96>>>(x_hi, x_lo, wq_hi, wq_lo, b_qkv,
                                               nullptr, qkv_hi, qkv_lo, TE_, E_);
    }
    {
        dim3 g(S_ / 64, H_, B_);          // 32 x 16 x 2
        flash_mma<<<g, 128, ASMEM>>>();
    }
    {
        dim3 g(E_ / 64, MTOT / 128);      // 16 x 32
        gemm_mma<0,0,64><<<g, 256, GSMEM_64>>>(o_hi, o_lo, wo_hi, wo_lo, b_o,
                                               out, nullptr, nullptr, E_, E_);
    }
}

// round 11
// speedup vs baseline: 2.3748x; 1.3731x over previous
#include <cuda_runtime.h>
#include <cuda_fp16.h>
#include <cstdint>

#define B_   2
#define S_   2048
#define H_   16
#define D_   64
#define E_   1024
#define TE_  3072
#define MTOT (B_ * S_)   // 4096

// ---------------------------------------------------------------------------
// Scratch (__device__ globals; no allocation allowed). All fp16 now.
// ---------------------------------------------------------------------------
__device__ __half g_qkv_h[(size_t)MTOT * TE_];   // QKV: Q single / K,V hi
__device__ __half g_qkv_l[(size_t)MTOT * TE_];   // K,V lo (Q slots unused)
__device__ __half g_o_h[(size_t)MTOT * E_];      // attention out, single fp16
__device__ __half g_x_h[(size_t)MTOT * E_];      // x, single fp16
__device__ __half g_wq_h[(size_t)TE_ * E_];
__device__ __half g_wq_l[(size_t)TE_ * E_];
__device__ __half g_wo_h[(size_t)E_ * E_];
__device__ __half g_wo_l[(size_t)E_ * E_];

// ---------------------------------------------------------------------------
// Helpers (sm_80-level PTX only)
// ---------------------------------------------------------------------------
__device__ __forceinline__ uint32_t smem_u32(const void* p) {
    uint32_t a;
    asm("{ .reg .u64 t; cvta.to.shared.u64 t, %1; cvt.u32.u64 %0, t; }" : "=r"(a) : "l"(p));
    return a;
}
__device__ __forceinline__ uint32_t pkf2(float a, float b) {   // packed half2
    __half2 t = __floats2half2_rn(a, b);
    return *reinterpret_cast<uint32_t*>(&t);
}
__device__ __forceinline__ void ldm_x4(uint32_t* r, uint32_t addr) {
    asm volatile("ldmatrix.sync.aligned.m8n8.x4.shared.b16 {%0,%1,%2,%3}, [%4];"
                 : "=r"(r[0]), "=r"(r[1]), "=r"(r[2]), "=r"(r[3]) : "r"(addr));
}
__device__ __forceinline__ void ldm_x4t(uint32_t* r, uint32_t addr) {
    asm volatile("ldmatrix.sync.aligned.m8n8.x4.trans.shared.b16 {%0,%1,%2,%3}, [%4];"
                 : "=r"(r[0]), "=r"(r[1]), "=r"(r[2]), "=r"(r[3]) : "r"(addr));
}
__device__ __forceinline__ void mma_f16(float* c, const uint32_t* a, const uint32_t* b) {
    asm volatile(
        "mma.sync.aligned.m16n8k16.row.col.f32.f16.f16.f32 "
        "{%0,%1,%2,%3}, {%4,%5,%6,%7}, {%8,%9}, {%0,%1,%2,%3};"
        : "+f"(c[0]), "+f"(c[1]), "+f"(c[2]), "+f"(c[3])
        : "r"(a[0]), "r"(a[1]), "r"(a[2]), "r"(a[3]), "r"(b[0]), "r"(b[1]));
}
__device__ __forceinline__ void cp_async16(uint32_t saddr, const void* gaddr) {
    asm volatile("cp.async.cg.shared.global [%0], [%1], 16;" :: "r"(saddr), "l"(gaddr) : "memory");
}
__device__ __forceinline__ void cp_commit() {
    asm volatile("cp.async.commit_group;" ::: "memory");
}
#define CP_WAIT(n) asm volatile("cp.async.wait_group %0;" :: "n"(n) : "memory")

// 128B-row XOR swizzle (8x16B groups), conflict-free for ldmatrix
__device__ __forceinline__ uint32_t sw128(uint32_t row, uint32_t kg) {
    return row * 128u + ((kg ^ (row & 7u)) << 4);
}

// ---------------------------------------------------------------------------
// Fused fp32 -> fp16 conversions: x (single), w_qkv (hi/lo), w_o (hi/lo)
// ---------------------------------------------------------------------------
#define N4_X  ((MTOT * E_) / 4)
#define N4_WQ ((TE_ * E_) / 4)
#define N4_WO ((E_ * E_) / 4)

__device__ __forceinline__ void split_pair(const float* in, __half* hi, __half* lo, int i)
{
    float4 v = ((const float4*)in)[i];
    __half h0 = __float2half_rn(v.x), h1 = __float2half_rn(v.y);
    __half h2 = __float2half_rn(v.z), h3 = __float2half_rn(v.w);
    uint2 hp = make_uint2(pkf2(v.x, v.y) /*placeholder*/, 0);
    // exact hi pack
    __half2 p0(h0, h1), p1(h2, h3);
    hp.x = *reinterpret_cast<uint32_t*>(&p0);
    hp.y = *reinterpret_cast<uint32_t*>(&p1);
    uint2 lp = make_uint2(pkf2(v.x - __half2float(h0), v.y - __half2float(h1)),
                          pkf2(v.z - __half2float(h2), v.w - __half2float(h3)));
    *(uint2*)(hi + (size_t)i * 4) = hp;
    *(uint2*)(lo + (size_t)i * 4) = lp;
}

__global__ __launch_bounds__(256)
void split_all(const float* __restrict__ x, const float* __restrict__ wq,
               const float* __restrict__ wo)
{
    int i = blockIdx.x * blockDim.x + threadIdx.x;
    if (i < N4_X) {
        float4 v = ((const float4*)x)[i];
        __half2 p0 = __floats2half2_rn(v.x, v.y);
        __half2 p1 = __floats2half2_rn(v.z, v.w);
        uint2 hp;
        hp.x = *reinterpret_cast<uint32_t*>(&p0);
        hp.y = *reinterpret_cast<uint32_t*>(&p1);
        *(uint2*)(g_x_h + (size_t)i * 4) = hp;
    } else if (i < N4_X + N4_WQ) {
        split_pair(wq, g_wq_h, g_wq_l, i - N4_X);
    } else if (i < N4_X + N4_WQ + N4_WO) {
        split_pair(wo, g_wo_h, g_wo_l, i - N4_X - N4_WQ);
    }
}

// ---------------------------------------------------------------------------
// HMMA fp16 2-term GEMM (NT): C = A[M,K]*(B1+B2)[N,K]^T + bias
// A single fp16, B split fp16 hi/lo. 128xBN tile, 8 warps, BK=64, 2-stage.
// MODE 0: fp32 C.  MODE 1: fp16 hi/lo outputs (QSCALE=1 prescales Q cols).
// ---------------------------------------------------------------------------
#define GA 16384                      // A tile: 128 rows x 128B

template <int BN>
__device__ __forceinline__ void gemm_issue(
    uint32_t sdst, const __half* Ax,
    const __half* Bh, const __half* Bl,
    int bm, int bn, int K, int t, int c)
{
    const int GB = BN * 128;
    const int koff = c * 128;
    // A: 1024 slots (128 rows x 8 kg)
    #pragma unroll
    for (int i = 0; i < 4; i++) {
        const int id = i * 256 + t;
        const int row = id >> 3, kg = id & 7;
        cp_async16(sdst + sw128(row, kg),
                   (const char*)(Ax + (size_t)(bm + row) * K) + kg * 16 + koff);
    }
    // B: 2*BN*8 slots
    #pragma unroll
    for (int i = 0; i < BN / 16; i++) {
        const int id = i * 256 + t;
        const int ishi = (id < BN * 8);
        const int idm = ishi ? id : id - BN * 8;
        const int row = idm >> 3, kg = idm & 7;
        const __half* base = ishi ? Bh : Bl;
        const uint32_t so = GA + (ishi ? 0 : GB) + sw128(row, kg);
        cp_async16(sdst + so, (const char*)(base + (size_t)(bn + row) * K) + kg * 16 + koff);
    }
    cp_commit();
}

template <int MODE, int QSCALE, int BN>
__global__ __launch_bounds__(256, 2)
void gemm_mma(const __half* __restrict__ Ax,
              const __half* __restrict__ Bh, const __half* __restrict__ Bl,
              const float* __restrict__ bias, float* __restrict__ C,
              __half* __restrict__ Chi, __half* __restrict__ Clo,
              int N, int K)
{
    constexpr int GB = BN * 128;
    constexpr int GSTAGE = GA + 2 * GB;
    constexpr int NTW = BN / 16;
    constexpr int NP = NTW / 2;

    extern __shared__ char smem[];
    const uint32_t sb = smem_u32(smem);
    const int t = threadIdx.x;
    const int wid = t >> 5;
    const int lane = t & 31;
    const int bm = blockIdx.y * 128;
    const int bn = blockIdx.x * BN;
    const int wm = (wid >> 1) * 32;
    const int wn = (wid & 1) * (BN / 2);

    float acc[2][NTW][4];
    #pragma unroll
    for (int mt = 0; mt < 2; mt++)
        #pragma unroll
        for (int nt = 0; nt < NTW; nt++)
            #pragma unroll
            for (int j = 0; j < 4; j++) acc[mt][nt][j] = 0.f;

    const int niter = K >> 6;

    gemm_issue<BN>(sb, Ax, Bh, Bl, bm, bn, K, t, 0);

    for (int c = 0; c < niter; c++) {
        if (c + 1 < niter) {
            gemm_issue<BN>(sb + ((c + 1) & 1) * GSTAGE, Ax, Bh, Bl, bm, bn, K, t, c + 1);
            CP_WAIT(1);
        } else {
            CP_WAIT(0);
        }
        __syncthreads();

        const uint32_t stage = sb + (c & 1) * GSTAGE;
        #pragma unroll
        for (int ks = 0; ks < 4; ks++) {
            uint32_t ah[2][4], bh[NP][4], bl[NP][4];
            #pragma unroll
            for (int mt = 0; mt < 2; mt++) {
                uint32_t off = sw128(wm + mt * 16 + (lane & 15), ks * 2 + (lane >> 4));
                ldm_x4(ah[mt], stage + off);
            }
            #pragma unroll
            for (int p = 0; p < NP; p++) {
                uint32_t off = sw128(wn + (p * 2 + (lane >> 4)) * 8 + (lane & 7),
                                     ks * 2 + ((lane >> 3) & 1));
                ldm_x4(bh[p], stage + GA + off);
                ldm_x4(bl[p], stage + GA + GB + off);
            }
            #pragma unroll
            for (int mt = 0; mt < 2; mt++)
                #pragma unroll
                for (int nt = 0; nt < NTW; nt++) {
                    const uint32_t* bhf = &bh[nt >> 1][(nt & 1) * 2];
                    const uint32_t* blf = &bl[nt >> 1][(nt & 1) * 2];
                    mma_f16(acc[mt][nt], ah[mt], bhf);
                    mma_f16(acc[mt][nt], ah[mt], blf);
                }
        }
        __syncthreads();
    }

    #pragma unroll
    for (int mt = 0; mt < 2; mt++) {
        const int r0 = bm + wm + mt * 16 + (lane >> 2);
        #pragma unroll
        for (int nt = 0; nt < NTW; nt++) {
            const int col = bn + wn + nt * 8 + (lane & 3) * 2;
            const float b0 = bias[col], b1 = bias[col + 1];
            float v00 = acc[mt][nt][0] + b0, v01 = acc[mt][nt][1] + b1;
            float v10 = acc[mt][nt][2] + b0, v11 = acc[mt][nt][3] + b1;
            if (MODE == 0) {
                *(float2*)&C[(size_t)r0 * N + col] = make_float2(v00, v01);
                *(float2*)&C[(size_t)(r0 + 8) * N + col] = make_float2(v10, v11);
            } else {
                if (QSCALE) {
                    const float qs = ((col % 192) < 64) ? 0.125f : 1.0f;
                    v00 *= qs; v01 *= qs; v10 *= qs; v11 *= qs;
                }
                __half h00 = __float2half_rn(v00), h01 = __float2half_rn(v01);
                __half h10 = __float2half_rn(v10), h11 = __float2half_rn(v11);
                __half2 p0(h00, h01), p1(h10, h11);
                *(uint32_t*)&Chi[(size_t)r0 * N + col] = *reinterpret_cast<uint32_t*>(&p0);
                *(uint32_t*)&Chi[(size_t)(r0 + 8) * N + col] = *reinterpret_cast<uint32_t*>(&p1);
                *(uint32_t*)&Clo[(size_t)r0 * N + col] =
                    pkf2(v00 - __half2float(h00), v01 - __half2float(h01));
                *(uint32_t*)&Clo[(size_t)(r0 + 8) * N + col] =
                    pkf2(v10 - __half2float(h10), v11 - __half2float(h11));
            }
        }
    }
}

// ---------------------------------------------------------------------------
// HMMA fp16 flash attention: 4 warps, 64 q-rows/CTA, 3 CTAs/SM.
// Q single fp16 (pre-scaled), K,V split fp16 hi/lo. 2 MMAs per logical mma.
// smem = 2 KV stages (64KB); Q parks in stage 1 during prologue.
// ---------------------------------------------------------------------------
#define AT      8192
#define ASTAGE  (4 * AT)
#define ASMEM   (2 * ASTAGE)   // 65536

__device__ __forceinline__ void attn_issue_kv(uint32_t sdst, int b, int h, int kt, int t)
{
    const size_t base_off = ((size_t)(b * S_ + kt * 64) * TE_ + h * (3 * D_)) * 2;
    #pragma unroll
    for (int i = 0; i < 16; i++) {
        const int tile = i >> 2;                  // 0:Kh 1:Kl 2:Vh 3:Vl
        const int row = (i & 3) * 16 + (t >> 3);
        const int kg = t & 7;
        const __half* arr = (tile & 1) ? g_qkv_l : g_qkv_h;
        const size_t go = base_off + (size_t)row * (TE_ * 2)
                        + (tile < 2 ? D_ : 2 * D_) * 2 + kg * 16;
        cp_async16(sdst + (uint32_t)tile * AT + sw128(row, kg), (const char*)arr + go);
    }
    cp_commit();
}

__global__ __launch_bounds__(128, 3)
void flash_mma()
{
    extern __shared__ char smem[];
    const uint32_t sb = smem_u32(smem);

    const int t = threadIdx.x;
    const int wid = t >> 5;
    const int lane = t & 31;
    const int qt = blockIdx.x, h = blockIdx.y, b = blockIdx.z;

    // prologue: Q (single tile) -> stage-1 Kh slot; KV(0) -> stage 0
    {
        const size_t qbase = ((size_t)(b * S_ + qt * 64) * TE_ + h * (3 * D_)) * 2;
        #pragma unroll
        for (int i = 0; i < 4; i++) {
            const int id = i * 128 + t;           // 0..511
            const int row = id >> 3, kg = id & 7;
            const size_t go = qbase + (size_t)row * (TE_ * 2) + kg * 16;
            cp_async16(sb + ASTAGE + sw128(row, kg), (const char*)g_qkv_h + go);
        }
        cp_commit();   // G0 = Q
    }
    attn_issue_kv(sb, b, h, 0, t);   // G1 = KV(0)

    CP_WAIT(1);        // Q landed
    __syncthreads();

    uint32_t aq[4][4];
    #pragma unroll
    for (int ks = 0; ks < 4; ks++) {
        uint32_t off = sw128(wid * 16 + (lane & 15), ks * 2 + (lane >> 4));
        ldm_x4(aq[ks], sb + ASTAGE + off);
    }
    __syncthreads();   // Q frags read before stage-1 overwritten by KV(1)

    float o[8][4];
    #pragma unroll
    for (int nt = 0; nt < 8; nt++)
        #pragma unroll
        for (int j = 0; j < 4; j++) o[nt][j] = 0.f;
    float m0 = -1e30f, m1 = -1e30f, l0 = 0.f, l1 = 0.f;

    const int NT = S_ / 64;
    for (int kt = 0; kt < NT; kt++) {
        if (kt + 1 < NT) {
            attn_issue_kv(sb + ((kt + 1) & 1) * ASTAGE, b, h, kt + 1, t);
            CP_WAIT(1);
        } else {
            CP_WAIT(0);
        }
        __syncthreads();

        const uint32_t st = sb + (kt & 1) * ASTAGE;
        const uint32_t stKh = st, stKl = st + AT, stVh = st + 2 * AT, stVl = st + 3 * AT;

        // ---- S = Q (K1+K2)^T, fp32 accum; Q pre-scaled ----
        float sc[8][4];
        #pragma unroll
        for (int nt = 0; nt < 8; nt++)
            #pragma unroll
            for (int j = 0; j < 4; j++) sc[nt][j] = 0.f;
        #pragma unroll
        for (int ks = 0; ks < 4; ks++) {
            #pragma unroll
            for (int p = 0; p < 4; p++) {
                uint32_t off = sw128((p * 2 + (lane >> 4)) * 8 + (lane & 7),
                                     ks * 2 + ((lane >> 3) & 1));
                uint32_t bh[4], bl[4];
                ldm_x4(bh, stKh + off);
                ldm_x4(bl, stKl + off);
                mma_f16(sc[2 * p], aq[ks], bh);
                mma_f16(sc[2 * p], aq[ks], bl);
                mma_f16(sc[2 * p + 1], aq[ks], bh + 2);
                mma_f16(sc[2 * p + 1], aq[ks], bl + 2);
            }
        }

        // ---- online softmax ----
        float rx0 = -1e30f, rx1 = -1e30f;
        #pragma unroll
        for (int nt = 0; nt < 8; nt++) {
            rx0 = fmaxf(rx0, fmaxf(sc[nt][0], sc[nt][1]));
            rx1 = fmaxf(rx1, fmaxf(sc[nt][2], sc[nt][3]));
        }
        rx0 = fmaxf(rx0, __shfl_xor_sync(0xffffffffu, rx0, 1));
        rx0 = fmaxf(rx0, __shfl_xor_sync(0xffffffffu, rx0, 2));
        rx1 = fmaxf(rx1, __shfl_xor_sync(0xffffffffu, rx1, 1));
        rx1 = fmaxf(rx1, __shfl_xor_sync(0xffffffffu, rx1, 2));

        const float mn0 = fmaxf(m0, rx0), mn1 = fmaxf(m1, rx1);
        const float s0 = __expf(m0 - mn0), s1 = __expf(m1 - mn1);
        m0 = mn0; m1 = mn1;
        #pragma unroll
        for (int nt = 0; nt < 8; nt++) {
            o[nt][0] *= s0; o[nt][1] *= s0;
            o[nt][2] *= s1; o[nt][3] *= s1;
        }
        float sum0 = 0.f, sum1 = 0.f;
        #pragma unroll
        for (int nt = 0; nt < 8; nt++) {
            sc[nt][0] = __expf(sc[nt][0] - mn0);
            sc[nt][1] = __expf(sc[nt][1] - mn0);
            sc[nt][2] = __expf(sc[nt][2] - mn1);
            sc[nt][3] = __expf(sc[nt][3] - mn1);
            sum0 += sc[nt][0] + sc[nt][1];
            sum1 += sc[nt][2] + sc[nt][3];
        }
        sum0 += __shfl_xor_sync(0xffffffffu, sum0, 1);
        sum0 += __shfl_xor_sync(0xffffffffu, sum0, 2);
        sum1 += __shfl_xor_sync(0xffffffffu, sum1, 1);
        sum1 += __shfl_xor_sync(0xffffffffu, sum1, 2);
        l0 = l0 * s0 + sum0;
        l1 = l1 * s1 + sum1;

        // ---- O += P (V1+V2), P single fp16 ----
        #pragma unroll
        for (int ks = 0; ks < 4; ks++) {
            uint32_t aph[4];
            {
                const int j0 = 2 * ks, j1 = 2 * ks + 1;
                aph[0] = pkf2(sc[j0][0], sc[j0][1]);
                aph[1] = pkf2(sc[j0][2], sc[j0][3]);
                aph[2] = pkf2(sc[j1][0], sc[j1][1]);
                aph[3] = pkf2(sc[j1][2], sc[j1][3]);
            }
            #pragma unroll
            for (int p = 0; p < 4; p++) {
                uint32_t off = sw128(ks * 16 + (lane & 15), 2 * p + (lane >> 4));
                uint32_t bh[4], bl[4];
                ldm_x4t(bh, stVh + off);
                ldm_x4t(bl, stVl + off);
                mma_f16(o[2 * p], aph, bh);
                mma_f16(o[2 * p], aph, bl);
                mma_f16(o[2 * p + 1], aph, bh + 2);
                mma_f16(o[2 * p + 1], aph, bl + 2);
            }
        }
        __syncthreads();
    }

    // ---- normalize, store single fp16 ----
    const float inv0 = 1.f / l0, inv1 = 1.f / l1;
    const int r0 = b * S_ + qt * 64 + wid * 16 + (lane >> 2);
    #pragma unroll
    for (int nt = 0; nt < 8; nt++) {
        const int col = h * D_ + nt * 8 + (lane & 3) * 2;
        *(uint32_t*)&g_o_h[(size_t)r0 * E_ + col] =
            pkf2(o[nt][0] * inv0, o[nt][1] * inv0);
        *(uint32_t*)&g_o_h[(size_t)(r0 + 8) * E_ + col] =
            pkf2(o[nt][2] * inv1, o[nt][3] * inv1);
    }
}

// ---------------------------------------------------------------------------
// Launch
// ---------------------------------------------------------------------------
extern "C" void kernel_launch(void* const* d_in, const int* in_sizes, int n_in,
                              void* d_out, int out_size)
{
    const float* x     = (const float*)d_in[0];
    const float* w_qkv = (const float*)d_in[1];
    const float* b_qkv = (const float*)d_in[2];
    const float* w_o   = (const float*)d_in[3];
    const float* b_o   = (const float*)d_in[4];
    float* out = (float*)d_out;

    __half *qkv_h, *qkv_l, *o_h, *x_h, *wq_h, *wq_l, *wo_h, *wo_l;
    cudaGetSymbolAddress((void**)&qkv_h, g_qkv_h);
    cudaGetSymbolAddress((void**)&qkv_l, g_qkv_l);
    cudaGetSymbolAddress((void**)&o_h, g_o_h);
    cudaGetSymbolAddress((void**)&x_h, g_x_h);
    cudaGetSymbolAddress((void**)&wq_h, g_wq_h);
    cudaGetSymbolAddress((void**)&wq_l, g_wq_l);
    cudaGetSymbolAddress((void**)&wo_h, g_wo_h);
    cudaGetSymbolAddress((void**)&wo_l, g_wo_l);

    constexpr int GSMEM_96 = 2 * (GA + 2 * 96 * 128);   // 81920
    constexpr int GSMEM_64 = 2 * (GA + 2 * 64 * 128);   // 65536

    cudaFuncSetAttribute((void*)gemm_mma<1,1,96>, cudaFuncAttributeMaxDynamicSharedMemorySize, GSMEM_96);
    cudaFuncSetAttribute((void*)gemm_mma<0,0,64>, cudaFuncAttributeMaxDynamicSharedMemorySize, GSMEM_64);
    cudaFuncSetAttribute((void*)flash_mma, cudaFuncAttributeMaxDynamicSharedMemorySize, ASMEM);

    {
        const int total = N4_X + N4_WQ + N4_WO;
        split_all<<<(total + 255) / 256, 256>>>(x, w_qkv, w_o);
    }

    {
        dim3 g(TE_ / 96, MTOT / 128);    // 32 x 32
        gemm_mma<1,1,96><<<g, 256, GSMEM_96>>>(x_h, wq_h, wq_l, b_qkv,
                                               nullptr, qkv_h, qkv_l, TE_, E_);
    }
    {
        dim3 g(S_ / 64, H_, B_);          // 32 x 16 x 2
        flash_mma<<<g, 128, ASMEM>>>();
    }
    {
        dim3 g(E_ / 64, MTOT / 128);      // 16 x 32
        gemm_mma<0,0,64><<<g, 256, GSMEM_64>>>(o_h, wo_h, wo_l, b_o,
                                               out, nullptr, nullptr, E_, E_);
    }
}

// round 12
// speedup vs baseline: 2.5869x; 1.0893x over previous
#include <cuda_runtime.h>
#include <cuda_fp16.h>
#include <cstdint>

#define B_   2
#define S_   2048
#define H_   16
#define D_   64
#define E_   1024
#define TE_  3072
#define MTOT (B_ * S_)   // 4096

// ---------------------------------------------------------------------------
// Scratch (__device__ globals; no allocation allowed). All fp16.
// ---------------------------------------------------------------------------
__device__ __half g_qkv_h[(size_t)MTOT * TE_];   // QKV: Q single / K,V hi
__device__ __half g_qkv_l[(size_t)MTOT * TE_];   // K lo (Q,V slots unused)
__device__ __half g_o_h[(size_t)MTOT * E_];      // attention out, single fp16
__device__ __half g_x_h[(size_t)MTOT * E_];      // x, single fp16
__device__ __half g_wq_h[(size_t)TE_ * E_];
__device__ __half g_wq_l[(size_t)TE_ * E_];
__device__ __half g_wo_h[(size_t)E_ * E_];
__device__ __half g_wo_l[(size_t)E_ * E_];

// ---------------------------------------------------------------------------
// Helpers (sm_80-level PTX only)
// ---------------------------------------------------------------------------
__device__ __forceinline__ uint32_t smem_u32(const void* p) {
    uint32_t a;
    asm("{ .reg .u64 t; cvta.to.shared.u64 t, %1; cvt.u32.u64 %0, t; }" : "=r"(a) : "l"(p));
    return a;
}
__device__ __forceinline__ uint32_t pkf2(float a, float b) {   // packed half2
    __half2 t = __floats2half2_rn(a, b);
    return *reinterpret_cast<uint32_t*>(&t);
}
__device__ __forceinline__ void ldm_x4(uint32_t* r, uint32_t addr) {
    asm volatile("ldmatrix.sync.aligned.m8n8.x4.shared.b16 {%0,%1,%2,%3}, [%4];"
                 : "=r"(r[0]), "=r"(r[1]), "=r"(r[2]), "=r"(r[3]) : "r"(addr));
}
__device__ __forceinline__ void ldm_x4t(uint32_t* r, uint32_t addr) {
    asm volatile("ldmatrix.sync.aligned.m8n8.x4.trans.shared.b16 {%0,%1,%2,%3}, [%4];"
                 : "=r"(r[0]), "=r"(r[1]), "=r"(r[2]), "=r"(r[3]) : "r"(addr));
}
__device__ __forceinline__ void mma_f16(float* c, const uint32_t* a, const uint32_t* b) {
    asm volatile(
        "mma.sync.aligned.m16n8k16.row.col.f32.f16.f16.f32 "
        "{%0,%1,%2,%3}, {%4,%5,%6,%7}, {%8,%9}, {%0,%1,%2,%3};"
        : "+f"(c[0]), "+f"(c[1]), "+f"(c[2]), "+f"(c[3])
        : "r"(a[0]), "r"(a[1]), "r"(a[2]), "r"(a[3]), "r"(b[0]), "r"(b[1]));
}
__device__ __forceinline__ void cp_async16(uint32_t saddr, const void* gaddr) {
    asm volatile("cp.async.cg.shared.global [%0], [%1], 16;" :: "r"(saddr), "l"(gaddr) : "memory");
}
__device__ __forceinline__ void cp_commit() {
    asm volatile("cp.async.commit_group;" ::: "memory");
}
#define CP_WAIT(n) asm volatile("cp.async.wait_group %0;" :: "n"(n) : "memory")

// 128B-row XOR swizzle (8x16B groups), conflict-free for ldmatrix
__device__ __forceinline__ uint32_t sw128(uint32_t row, uint32_t kg) {
    return row * 128u + ((kg ^ (row & 7u)) << 4);
}

// ---------------------------------------------------------------------------
// Fused fp32 -> fp16 conversions: x (single), w_qkv (hi/lo), w_o (hi/lo)
// ---------------------------------------------------------------------------
#define N4_X  ((MTOT * E_) / 4)
#define N4_WQ ((TE_ * E_) / 4)
#define N4_WO ((E_ * E_) / 4)

__device__ __forceinline__ void split_pair(const float* in, __half* hi, __half* lo, int i)
{
    float4 v = ((const float4*)in)[i];
    __half h0 = __float2half_rn(v.x), h1 = __float2half_rn(v.y);
    __half h2 = __float2half_rn(v.z), h3 = __float2half_rn(v.w);
    __half2 p0(h0, h1), p1(h2, h3);
    uint2 hp;
    hp.x = *reinterpret_cast<uint32_t*>(&p0);
    hp.y = *reinterpret_cast<uint32_t*>(&p1);
    uint2 lp = make_uint2(pkf2(v.x - __half2float(h0), v.y - __half2float(h1)),
                          pkf2(v.z - __half2float(h2), v.w - __half2float(h3)));
    *(uint2*)(hi + (size_t)i * 4) = hp;
    *(uint2*)(lo + (size_t)i * 4) = lp;
}

__global__ __launch_bounds__(256)
void split_all(const float* __restrict__ x, const float* __restrict__ wq,
               const float* __restrict__ wo)
{
    int i = blockIdx.x * blockDim.x + threadIdx.x;
    if (i < N4_X) {
        float4 v = ((const float4*)x)[i];
        __half2 p0 = __floats2half2_rn(v.x, v.y);
        __half2 p1 = __floats2half2_rn(v.z, v.w);
        uint2 hp;
        hp.x = *reinterpret_cast<uint32_t*>(&p0);
        hp.y = *reinterpret_cast<uint32_t*>(&p1);
        *(uint2*)(g_x_h + (size_t)i * 4) = hp;
    } else if (i < N4_X + N4_WQ) {
        split_pair(wq, g_wq_h, g_wq_l, i - N4_X);
    } else if (i < N4_X + N4_WQ + N4_WO) {
        split_pair(wo, g_wo_h, g_wo_l, i - N4_X - N4_WQ);
    }
}

// ---------------------------------------------------------------------------
// HMMA fp16 2-term GEMM (NT): C = A[M,K]*(B1+B2)[N,K]^T + bias
// A single fp16, B split fp16 hi/lo. 128xBN tile, 8 warps, BK=64, 2-stage.
// MODE 0: fp32 C.  MODE 1: fp16 hi/lo outputs (QSCALE=1 prescales Q cols).
// ---------------------------------------------------------------------------
#define GA 16384                      // A tile: 128 rows x 128B

template <int BN>
__device__ __forceinline__ void gemm_issue(
    uint32_t sdst, const __half* Ax,
    const __half* Bh, const __half* Bl,
    int bm, int bn, int K, int t, int c)
{
    const int GB = BN * 128;
    const int koff = c * 128;
    #pragma unroll
    for (int i = 0; i < 4; i++) {
        const int id = i * 256 + t;
        const int row = id >> 3, kg = id & 7;
        cp_async16(sdst + sw128(row, kg),
                   (const char*)(Ax + (size_t)(bm + row) * K) + kg * 16 + koff);
    }
    #pragma unroll
    for (int i = 0; i < BN / 16; i++) {
        const int id = i * 256 + t;
        const int ishi = (id < BN * 8);
        const int idm = ishi ? id : id - BN * 8;
        const int row = idm >> 3, kg = idm & 7;
        const __half* base = ishi ? Bh : Bl;
        const uint32_t so = GA + (ishi ? 0 : GB) + sw128(row, kg);
        cp_async16(sdst + so, (const char*)(base + (size_t)(bn + row) * K) + kg * 16 + koff);
    }
    cp_commit();
}

template <int MODE, int QSCALE, int BN>
__global__ __launch_bounds__(256, 2)
void gemm_mma(const __half* __restrict__ Ax,
              const __half* __restrict__ Bh, const __half* __restrict__ Bl,
              const float* __restrict__ bias, float* __restrict__ C,
              __half* __restrict__ Chi, __half* __restrict__ Clo,
              int N, int K)
{
    constexpr int GB = BN * 128;
    constexpr int GSTAGE = GA + 2 * GB;
    constexpr int NTW = BN / 16;
    constexpr int NP = NTW / 2;

    extern __shared__ char smem[];
    const uint32_t sb = smem_u32(smem);
    const int t = threadIdx.x;
    const int wid = t >> 5;
    const int lane = t & 31;
    const int bm = blockIdx.y * 128;
    const int bn = blockIdx.x * BN;
    const int wm = (wid >> 1) * 32;
    const int wn = (wid & 1) * (BN / 2);

    float acc[2][NTW][4];
    #pragma unroll
    for (int mt = 0; mt < 2; mt++)
        #pragma unroll
        for (int nt = 0; nt < NTW; nt++)
            #pragma unroll
            for (int j = 0; j < 4; j++) acc[mt][nt][j] = 0.f;

    const int niter = K >> 6;

    gemm_issue<BN>(sb, Ax, Bh, Bl, bm, bn, K, t, 0);

    for (int c = 0; c < niter; c++) {
        if (c + 1 < niter) {
            gemm_issue<BN>(sb + ((c + 1) & 1) * GSTAGE, Ax, Bh, Bl, bm, bn, K, t, c + 1);
            CP_WAIT(1);
        } else {
            CP_WAIT(0);
        }
        __syncthreads();

        const uint32_t stage = sb + (c & 1) * GSTAGE;
        #pragma unroll
        for (int ks = 0; ks < 4; ks++) {
            uint32_t ah[2][4], bh[NP][4], bl[NP][4];
            #pragma unroll
            for (int mt = 0; mt < 2; mt++) {
                uint32_t off = sw128(wm + mt * 16 + (lane & 15), ks * 2 + (lane >> 4));
                ldm_x4(ah[mt], stage + off);
            }
            #pragma unroll
            for (int p = 0; p < NP; p++) {
                uint32_t off = sw128(wn + (p * 2 + (lane >> 4)) * 8 + (lane & 7),
                                     ks * 2 + ((lane >> 3) & 1));
                ldm_x4(bh[p], stage + GA + off);
                ldm_x4(bl[p], stage + GA + GB + off);
            }
            #pragma unroll
            for (int mt = 0; mt < 2; mt++)
                #pragma unroll
                for (int nt = 0; nt < NTW; nt++) {
                    const uint32_t* bhf = &bh[nt >> 1][(nt & 1) * 2];
                    const uint32_t* blf = &bl[nt >> 1][(nt & 1) * 2];
                    mma_f16(acc[mt][nt], ah[mt], bhf);
                    mma_f16(acc[mt][nt], ah[mt], blf);
                }
        }
        __syncthreads();
    }

    #pragma unroll
    for (int mt = 0; mt < 2; mt++) {
        const int r0 = bm + wm + mt * 16 + (lane >> 2);
        #pragma unroll
        for (int nt = 0; nt < NTW; nt++) {
            const int col = bn + wn + nt * 8 + (lane & 3) * 2;
            const float b0 = bias[col], b1 = bias[col + 1];
            float v00 = acc[mt][nt][0] + b0, v01 = acc[mt][nt][1] + b1;
            float v10 = acc[mt][nt][2] + b0, v11 = acc[mt][nt][3] + b1;
            if (MODE == 0) {
                *(float2*)&C[(size_t)r0 * N + col] = make_float2(v00, v01);
                *(float2*)&C[(size_t)(r0 + 8) * N + col] = make_float2(v10, v11);
            } else {
                if (QSCALE) {
                    const float qs = ((col % 192) < 64) ? 0.125f : 1.0f;
                    v00 *= qs; v01 *= qs; v10 *= qs; v11 *= qs;
                }
                __half h00 = __float2half_rn(v00), h01 = __float2half_rn(v01);
                __half h10 = __float2half_rn(v10), h11 = __float2half_rn(v11);
                __half2 p0(h00, h01), p1(h10, h11);
                *(uint32_t*)&Chi[(size_t)r0 * N + col] = *reinterpret_cast<uint32_t*>(&p0);
                *(uint32_t*)&Chi[(size_t)(r0 + 8) * N + col] = *reinterpret_cast<uint32_t*>(&p1);
                *(uint32_t*)&Clo[(size_t)r0 * N + col] =
                    pkf2(v00 - __half2float(h00), v01 - __half2float(h01));
                *(uint32_t*)&Clo[(size_t)(r0 + 8) * N + col] =
                    pkf2(v10 - __half2float(h10), v11 - __half2float(h11));
            }
        }
    }
}

// ---------------------------------------------------------------------------
// HMMA fp16 flash attention: 4 warps, 64 q-rows/CTA, 4 CTAs/SM.
// Q single fp16 (pre-scaled), K split hi/lo, V single fp16.
// smem = 2 stages x {Kh, Kl, Vh} = 48KB; Q parks in stage 1 during prologue.
// ---------------------------------------------------------------------------
#define AT      8192
#define ASTAGE  (3 * AT)       // Kh, Kl, Vh
#define ASMEM   (2 * ASTAGE)   // 49152

__device__ __forceinline__ void attn_issue_kv(uint32_t sdst, int b, int h, int kt, int t)
{
    const size_t base_off = ((size_t)(b * S_ + kt * 64) * TE_ + h * (3 * D_)) * 2;
    // 1536 slots (3 tiles x 64 rows x 8 kg) over 128 threads -> 12 each
    #pragma unroll
    for (int i = 0; i < 12; i++) {
        const int id = i * 128 + t;
        const int tile = id >> 9;                 // 0:Kh 1:Kl 2:Vh
        const int row = (id >> 3) & 63;
        const int kg = id & 7;
        const __half* arr = (tile == 1) ? g_qkv_l : g_qkv_h;
        const size_t go = base_off + (size_t)row * (TE_ * 2)
                        + ((tile < 2) ? D_ : 2 * D_) * 2 + kg * 16;
        cp_async16(sdst + (uint32_t)tile * AT + sw128(row, kg), (const char*)arr + go);
    }
    cp_commit();
}

__global__ __launch_bounds__(128, 4)
void flash_mma()
{
    extern __shared__ char smem[];
    const uint32_t sb = smem_u32(smem);

    const int t = threadIdx.x;
    const int wid = t >> 5;
    const int lane = t & 31;
    const int qt = blockIdx.x, h = blockIdx.y, b = blockIdx.z;

    // prologue: Q -> stage-1 Kh slot; KV(0) -> stage 0
    {
        const size_t qbase = ((size_t)(b * S_ + qt * 64) * TE_ + h * (3 * D_)) * 2;
        #pragma unroll
        for (int i = 0; i < 4; i++) {
            const int id = i * 128 + t;           // 0..511
            const int row = id >> 3, kg = id & 7;
            const size_t go = qbase + (size_t)row * (TE_ * 2) + kg * 16;
            cp_async16(sb + ASTAGE + sw128(row, kg), (const char*)g_qkv_h + go);
        }
        cp_commit();   // G0 = Q
    }
    attn_issue_kv(sb, b, h, 0, t);   // G1 = KV(0)

    CP_WAIT(1);        // Q landed
    __syncthreads();

    uint32_t aq[4][4];
    #pragma unroll
    for (int ks = 0; ks < 4; ks++) {
        uint32_t off = sw128(wid * 16 + (lane & 15), ks * 2 + (lane >> 4));
        ldm_x4(aq[ks], sb + ASTAGE + off);
    }
    __syncthreads();   // Q frags read before stage-1 overwritten by KV(1)

    float o[8][4];
    #pragma unroll
    for (int nt = 0; nt < 8; nt++)
        #pragma unroll
        for (int j = 0; j < 4; j++) o[nt][j] = 0.f;
    float m0 = -1e30f, m1 = -1e30f, l0 = 0.f, l1 = 0.f;

    const int NT = S_ / 64;
    for (int kt = 0; kt < NT; kt++) {
        if (kt + 1 < NT) {
            attn_issue_kv(sb + ((kt + 1) & 1) * ASTAGE, b, h, kt + 1, t);
            CP_WAIT(1);
        } else {
            CP_WAIT(0);
        }
        __syncthreads();

        const uint32_t st = sb + (kt & 1) * ASTAGE;
        const uint32_t stKh = st, stKl = st + AT, stVh = st + 2 * AT;

        // ---- S = Q (K1+K2)^T, fp32 accum; Q pre-scaled ----
        float sc[8][4];
        #pragma unroll
        for (int nt = 0; nt < 8; nt++)
            #pragma unroll
            for (int j = 0; j < 4; j++) sc[nt][j] = 0.f;
        #pragma unroll
        for (int ks = 0; ks < 4; ks++) {
            #pragma unroll
            for (int p = 0; p < 4; p++) {
                uint32_t off = sw128((p * 2 + (lane >> 4)) * 8 + (lane & 7),
                                     ks * 2 + ((lane >> 3) & 1));
                uint32_t bh[4], bl[4];
                ldm_x4(bh, stKh + off);
                ldm_x4(bl, stKl + off);
                mma_f16(sc[2 * p], aq[ks], bh);
                mma_f16(sc[2 * p], aq[ks], bl);
                mma_f16(sc[2 * p + 1], aq[ks], bh + 2);
                mma_f16(sc[2 * p + 1], aq[ks], bl + 2);
            }
        }

        // ---- online softmax ----
        float rx0 = -1e30f, rx1 = -1e30f;
        #pragma unroll
        for (int nt = 0; nt < 8; nt++) {
            rx0 = fmaxf(rx0, fmaxf(sc[nt][0], sc[nt][1]));
            rx1 = fmaxf(rx1, fmaxf(sc[nt][2], sc[nt][3]));
        }
        rx0 = fmaxf(rx0, __shfl_xor_sync(0xffffffffu, rx0, 1));
        rx0 = fmaxf(rx0, __shfl_xor_sync(0xffffffffu, rx0, 2));
        rx1 = fmaxf(rx1, __shfl_xor_sync(0xffffffffu, rx1, 1));
        rx1 = fmaxf(rx1, __shfl_xor_sync(0xffffffffu, rx1, 2));

        const float mn0 = fmaxf(m0, rx0), mn1 = fmaxf(m1, rx1);
        const float s0 = __expf(m0 - mn0), s1 = __expf(m1 - mn1);
        m0 = mn0; m1 = mn1;
        #pragma unroll
        for (int nt = 0; nt < 8; nt++) {
            o[nt][0] *= s0; o[nt][1] *= s0;
            o[nt][2] *= s1; o[nt][3] *= s1;
        }
        float sum0 = 0.f, sum1 = 0.f;
        #pragma unroll
        for (int nt = 0; nt < 8; nt++) {
            sc[nt][0] = __expf(sc[nt][0] - mn0);
            sc[nt][1] = __expf(sc[nt][1] - mn0);
            sc[nt][2] = __expf(sc[nt][2] - mn1);
            sc[nt][3] = __expf(sc[nt][3] - mn1);
            sum0 += sc[nt][0] + sc[nt][1];
            sum1 += sc[nt][2] + sc[nt][3];
        }
        sum0 += __shfl_xor_sync(0xffffffffu, sum0, 1);
        sum0 += __shfl_xor_sync(0xffffffffu, sum0, 2);
        sum1 += __shfl_xor_sync(0xffffffffu, sum1, 1);
        sum1 += __shfl_xor_sync(0xffffffffu, sum1, 2);
        l0 = l0 * s0 + sum0;
        l1 = l1 * s1 + sum1;

        // ---- O += P V, P single fp16, V single fp16 ----
        #pragma unroll
        for (int ks = 0; ks < 4; ks++) {
            uint32_t aph[4];
            {
                const int j0 = 2 * ks, j1 = 2 * ks + 1;
                aph[0] = pkf2(sc[j0][0], sc[j0][1]);
                aph[1] = pkf2(sc[j0][2], sc[j0][3]);
                aph[2] = pkf2(sc[j1][0], sc[j1][1]);
                aph[3] = pkf2(sc[j1][2], sc[j1][3]);
            }
            #pragma unroll
            for (int p = 0; p < 4; p++) {
                uint32_t off = sw128(ks * 16 + (lane & 15), 2 * p + (lane >> 4));
                uint32_t bh[4];
                ldm_x4t(bh, stVh + off);
                mma_f16(o[2 * p], aph, bh);
                mma_f16(o[2 * p + 1], aph, bh + 2);
            }
        }
        __syncthreads();
    }

    // ---- normalize, store single fp16 ----
    const float inv0 = 1.f / l0, inv1 = 1.f / l1;
    const int r0 = b * S_ + qt * 64 + wid * 16 + (lane >> 2);
    #pragma unroll
    for (int nt = 0; nt < 8; nt++) {
        const int col = h * D_ + nt * 8 + (lane & 3) * 2;
        *(uint32_t*)&g_o_h[(size_t)r0 * E_ + col] =
            pkf2(o[nt][0] * inv0, o[nt][1] * inv0);
        *(uint32_t*)&g_o_h[(size_t)(r0 + 8) * E_ + col] =
            pkf2(o[nt][2] * inv1, o[nt][3] * inv1);
    }
}

// ---------------------------------------------------------------------------
// Launch
// ---------------------------------------------------------------------------
extern "C" void kernel_launch(void* const* d_in, const int* in_sizes, int n_in,
                              void* d_out, int out_size)
{
    const float* x     = (const float*)d_in[0];
    const float* w_qkv = (const float*)d_in[1];
    const float* b_qkv = (const float*)d_in[2];
    const float* w_o   = (const float*)d_in[3];
    const float* b_o   = (const float*)d_in[4];
    float* out = (float*)d_out;

    __half *qkv_h, *qkv_l, *o_h, *x_h, *wq_h, *wq_l, *wo_h, *wo_l;
    cudaGetSymbolAddress((void**)&qkv_h, g_qkv_h);
    cudaGetSymbolAddress((void**)&qkv_l, g_qkv_l);
    cudaGetSymbolAddress((void**)&o_h, g_o_h);
    cudaGetSymbolAddress((void**)&x_h, g_x_h);
    cudaGetSymbolAddress((void**)&wq_h, g_wq_h);
    cudaGetSymbolAddress((void**)&wq_l, g_wq_l);
    cudaGetSymbolAddress((void**)&wo_h, g_wo_h);
    cudaGetSymbolAddress((void**)&wo_l, g_wo_l);

    constexpr int GSMEM_96 = 2 * (GA + 2 * 96 * 128);   // 81920
    constexpr int GSMEM_64 = 2 * (GA + 2 * 64 * 128);   // 65536

    cudaFuncSetAttribute((void*)gemm_mma<1,1,96>, cudaFuncAttributeMaxDynamicSharedMemorySize, GSMEM_96);
    cudaFuncSetAttribute((void*)gemm_mma<0,0,64>, cudaFuncAttributeMaxDynamicSharedMemorySize, GSMEM_64);
    cudaFuncSetAttribute((void*)flash_mma, cudaFuncAttributeMaxDynamicSharedMemorySize, ASMEM);

    {
        const int total = N4_X + N4_WQ + N4_WO;
        split_all<<<(total + 255) / 256, 256>>>(x, w_qkv, w_o);
    }

    {
        dim3 g(TE_ / 96, MTOT / 128);    // 32 x 32
        gemm_mma<1,1,96><<<g, 256, GSMEM_96>>>(x_h, wq_h, wq_l, b_qkv,
                                               nullptr, qkv_h, qkv_l, TE_, E_);
    }
    {
        dim3 g(S_ / 64, H_, B_);          // 32 x 16 x 2
        flash_mma<<<g, 128, ASMEM>>>();
    }
    {
        dim3 g(E_ / 64, MTOT / 128);      // 16 x 32
        gemm_mma<0,0,64><<<g, 256, GSMEM_64>>>(o_h, wo_h, wo_l, b_o,
                                               out, nullptr, nullptr, E_, E_);
    }
}